// round 7
// baseline (speedup 1.0000x reference)
#include <cuda_runtime.h>
#include <cuda_bf16.h>
#include <cstddef>
#include <cstdint>
#include <math.h>

// ---------------------------------------------------------------------------
// SpatialTranscriptomicsDecoder — GB300 sm_103a. Round 7.
// mma.sync bf16x2-split GEMM, 4-stage cp.async pipeline, BM={128,64} templates.
// ---------------------------------------------------------------------------

static constexpr int B = 2, P = 196, FD = 1024, G = 2000, D = 256, H = 8, NL = 4, HALF = 128;
static constexpr float ATT_SCALE = 0.17677669529663687f;
static constexpr int MQ = B * G;   // 4000
static constexpr int MP = B * P;   // 392

// ---------------- fp32 workspace ----------------
static constexpr size_t OFF_PATCH = 0;
static constexpr size_t OFF_TMP   = OFF_PATCH + (size_t)MP * D;
static constexpr size_t OFF_PE    = OFF_TMP   + (size_t)MP * D;
static constexpr size_t OFF_KV    = OFF_PE    + (size_t)MP * D;
static constexpr size_t OFF_Q     = OFF_KV    + (size_t)MP * 2 * D;
static constexpr size_t OFF_QB    = OFF_Q     + (size_t)MQ * D;
static constexpr size_t OFF_ATT   = OFF_QB    + (size_t)MQ * D;
static constexpr size_t OFF_QP    = OFF_ATT   + (size_t)MQ * D;
static constexpr size_t OFF_PP    = OFF_QP    + (size_t)MQ * HALF;
static constexpr size_t OFF_WT_PATCH = OFF_PP + (size_t)MP * HALF;
static constexpr size_t OFF_WT_PE    = OFF_WT_PATCH + 256 * 1024;
static constexpr size_t OFF_WT_WKV   = OFF_WT_PE    + 256 * 256;
static constexpr size_t OFF_WT_HEAD  = OFF_WT_WKV   + (size_t)NL * 512 * 256;
static constexpr size_t WS_TOTAL     = OFF_WT_HEAD  + 128 * 256;
__device__ float g_ws[WS_TOTAL];

// ---------------- bf16 workspace ----------------
static constexpr size_t BQ  = (size_t)MQ * D;
static constexpr size_t BF_QH  = 0;
static constexpr size_t BF_QL  = BF_QH + BQ;
static constexpr size_t BF_L1H = BF_QL + BQ;
static constexpr size_t BF_L1L = BF_L1H + BQ;
static constexpr size_t BF_CXH = BF_L1L + BQ;
static constexpr size_t BF_CXL = BF_CXH + BQ;
static constexpr size_t BF_FH  = BF_CXL + BQ;
static constexpr size_t BF_FL  = BF_FH + (size_t)MQ * 4 * D;
static constexpr size_t BF_WQH = BF_FL + (size_t)MQ * 4 * D;
static constexpr size_t BF_WQL = BF_WQH + (size_t)NL * D * D;
static constexpr size_t BF_WOH = BF_WQL + (size_t)NL * D * D;
static constexpr size_t BF_WOL = BF_WOH + (size_t)NL * D * D;
static constexpr size_t BF_F1H = BF_WOL + (size_t)NL * D * D;
static constexpr size_t BF_F1L = BF_F1H + (size_t)NL * 4 * D * D;
static constexpr size_t BF_F2H = BF_F1L + (size_t)NL * 4 * D * D;
static constexpr size_t BF_F2L = BF_F2H + (size_t)NL * 4 * D * D;
static constexpr size_t BF_HDH = BF_F2L + (size_t)NL * 4 * D * D;
static constexpr size_t BF_HDL = BF_HDH + (size_t)HALF * D;
static constexpr size_t BF_TOTAL = BF_HDL + (size_t)HALF * D;
__device__ __nv_bfloat16 g_bf[BF_TOTAL];

// ---------------- helpers ----------------
__device__ __forceinline__ float geluf(float x) {
    return 0.5f * x * (1.0f + erff(x * 0.7071067811865476f));
}
__device__ __forceinline__ float softplusf(float x) {
    return fmaxf(x, 0.0f) + __logf(1.0f + __expf(-fabsf(x)));
}
__device__ __forceinline__ void splitf(float v, __nv_bfloat16& h, __nv_bfloat16& l) {
    h = __float2bfloat16(v);
    l = __float2bfloat16(v - __bfloat162float(h));
}
__device__ __forceinline__ float2 u2f2(unsigned long long u) {
    float2 f;
    asm("mov.b64 {%0, %1}, %2;" : "=f"(f.x), "=f"(f.y) : "l"(u));
    return f;
}
__device__ __forceinline__ void fma2(unsigned long long& acc, unsigned long long a,
                                     unsigned long long b) {
    asm("fma.rn.f32x2 %0, %1, %2, %0;" : "+l"(acc) : "l"(a), "l"(b));
}
__device__ __forceinline__ void cpa16(unsigned int dst, const void* src, bool ok) {
    asm volatile("cp.async.ca.shared.global [%0], [%1], 16, %2;"
                 :: "r"(dst), "l"(src), "r"(ok ? 16 : 0) : "memory");
}
__device__ __forceinline__ void cpa_commit() {
    asm volatile("cp.async.commit_group;" ::: "memory");
}
template<int Ng> __device__ __forceinline__ void cpa_waitg() {
    asm volatile("cp.async.wait_group %0;" :: "n"(Ng) : "memory");
}
__device__ __forceinline__ void ldm4(unsigned& r0, unsigned& r1, unsigned& r2, unsigned& r3,
                                     unsigned addr) {
    asm volatile("ldmatrix.sync.aligned.m8n8.x4.shared.b16 {%0,%1,%2,%3}, [%4];"
                 : "=r"(r0), "=r"(r1), "=r"(r2), "=r"(r3) : "r"(addr));
}
__device__ __forceinline__ void mma16816(float* d, const unsigned* a, unsigned b0, unsigned b1) {
    asm volatile(
        "mma.sync.aligned.m16n8k16.row.col.f32.bf16.bf16.f32 "
        "{%0,%1,%2,%3}, {%4,%5,%6,%7}, {%8,%9}, {%0,%1,%2,%3};"
        : "+f"(d[0]), "+f"(d[1]), "+f"(d[2]), "+f"(d[3])
        : "r"(a[0]), "r"(a[1]), "r"(a[2]), "r"(a[3]), "r"(b0), "r"(b1));
}

// ---------------------------------------------------------------------------
// mma.sync GEMM: C[M,N] = act( (Ah+Al) @ (Wh+Wl)^T + bias ); 3-term comp.
// grid (N/64, ceil(M/BM)), 256 threads. 4-stage cp.async pipeline.
// BM=128: warps 4x2 (tile 32x32). BM=64: warps 2x4 (tile 32x16).
// ---------------------------------------------------------------------------
template<int BM>
__global__ void __launch_bounds__(256) mma_gemm_kernel(
    const __nv_bfloat16* __restrict__ Ah, const __nv_bfloat16* __restrict__ Al,
    const __nv_bfloat16* __restrict__ Wh, const __nv_bfloat16* __restrict__ Wl,
    const float* __restrict__ bias,
    float* __restrict__ Cf, __nv_bfloat16* __restrict__ Ch, __nv_bfloat16* __restrict__ Cl,
    int M, int N, int K, int act)
{
    constexpr int STR = 24;                       // bf16 per smem row (48B)
    constexpr int szA = BM * STR * 2;             // bytes per A (h or l) per stage
    constexpr int szW = 64 * STR * 2;
    constexpr int STG = 2 * szA + 2 * szW;        // bytes per stage
    constexpr int MT  = 2;                        // m16 tiles per warp
    constexpr int WMASK  = (BM == 128) ? 3 : 1;
    constexpr int WSHIFT = (BM == 128) ? 2 : 1;
    constexpr int NT8 = (BM == 128) ? 4 : 2;      // n8 tiles per warp
    constexpr int NP  = NT8 / 2;                  // B ldmatrix.x4 per h/l
    constexpr int NLD = (BM == 128) ? 3 : 2;      // cp.async per thread per stage

    extern __shared__ char smem[];
    const unsigned sb = (unsigned)__cvta_generic_to_shared(smem);

    const int tid = threadIdx.x;
    const int lane = tid & 31, wid = tid >> 5;
    const int wm = wid & WMASK, wn = wid >> WSHIFT;
    const int bm = blockIdx.y * BM;
    const int bn = blockIdx.x * 64;
    const int NC = K >> 4;                        // always >= 16 here

    // ---- per-thread load descriptors ----
    unsigned off[NLD];
    const __nv_bfloat16* src[NLD];
    bool okf[NLD];
    if (BM == 128) {
        const int rowA = tid >> 1, segA = tid & 1;
        const bool aok = (bm + rowA) < M;
        off[0] = (unsigned)((rowA * STR + segA * 8) * 2);
        src[0] = Ah + (size_t)(bm + rowA) * K + segA * 8; okf[0] = aok;
        off[1] = (unsigned)(szA + (rowA * STR + segA * 8) * 2);
        src[1] = Al + (size_t)(bm + rowA) * K + segA * 8; okf[1] = aok;
        const int rowW = (tid & 127) >> 1, segW = tid & 1;
        off[NLD - 1] = (unsigned)(2 * szA + (tid < 128 ? 0 : szW) + (rowW * STR + segW * 8) * 2);
        src[NLD - 1] = (tid < 128 ? Wh : Wl) + (size_t)(bn + rowW) * K + segW * 8;
        okf[NLD - 1] = true;
    } else {
        const int rowA = (tid & 127) >> 1, segA = tid & 1;
        const bool aok = (bm + rowA) < M;
        off[0] = (unsigned)((tid < 128 ? 0 : szA) + (rowA * STR + segA * 8) * 2);
        src[0] = (tid < 128 ? Ah : Al) + (size_t)(bm + rowA) * K + segA * 8; okf[0] = aok;
        off[1] = (unsigned)(2 * szA + (tid < 128 ? 0 : szW) + (rowA * STR + segA * 8) * 2);
        src[1] = (tid < 128 ? Wh : Wl) + (size_t)(bn + rowA) * K + segA * 8; okf[1] = true;
    }

    auto loadChunk = [&](int kc, int s) {
        const int o = kc << 4;
        const unsigned base = sb + s * STG;
#pragma unroll
        for (int i = 0; i < NLD; i++) cpa16(base + off[i], src[i] + o, okf[i]);
        cpa_commit();
    };

    // ---- ldmatrix within-stage offsets ----
    unsigned aoffH[MT], boffH[NP];
    {
        const int ar = wm * 32 + (lane & 15);
        const int ak = (lane >> 4) * 8;
        const int br = wn * (NT8 * 8) + (lane & 7) + ((lane >> 4) << 3);
        const int bk = ((lane >> 3) & 1) * 8;
#pragma unroll
        for (int t = 0; t < MT; t++) aoffH[t] = (unsigned)(((ar + t * 16) * STR + ak) * 2);
#pragma unroll
        for (int p = 0; p < NP; p++) boffH[p] = (unsigned)(2 * szA + ((br + p * 16) * STR + bk) * 2);
    }

    // ---- prologue: stage 0..2 ----
    loadChunk(0, 0);
    loadChunk(1, 1);
    loadChunk(2, 2);

    float acc[MT][NT8][4];
#pragma unroll
    for (int i = 0; i < MT; i++)
#pragma unroll
        for (int j = 0; j < NT8; j++)
#pragma unroll
            for (int k = 0; k < 4; k++) acc[i][j][k] = 0.f;

    for (int kc = 0; kc < NC; kc++) {
        cpa_waitg<2>();
        __syncthreads();
        const int s = kc & 3;
        const int nk = kc + 3;
        if (nk < NC) loadChunk(nk, nk & 3);
        else cpa_commit();                        // keep group accounting uniform

        const unsigned stg = sb + s * STG;
        unsigned ah[MT][4], al[MT][4], bh[NP][4], bl[NP][4];
#pragma unroll
        for (int t = 0; t < MT; t++) {
            ldm4(ah[t][0], ah[t][1], ah[t][2], ah[t][3], stg + aoffH[t]);
            ldm4(al[t][0], al[t][1], al[t][2], al[t][3], stg + aoffH[t] + szA);
        }
#pragma unroll
        for (int p = 0; p < NP; p++) {
            ldm4(bh[p][0], bh[p][1], bh[p][2], bh[p][3], stg + boffH[p]);
            ldm4(bl[p][0], bl[p][1], bl[p][2], bl[p][3], stg + boffH[p] + szW);
        }
#pragma unroll
        for (int mt = 0; mt < MT; mt++) {
#pragma unroll
            for (int nt = 0; nt < NT8; nt++) {
                const int p = nt >> 1, nh = (nt & 1) << 1;
                mma16816(acc[mt][nt], ah[mt], bh[p][nh], bh[p][nh + 1]);
                mma16816(acc[mt][nt], ah[mt], bl[p][nh], bl[p][nh + 1]);
                mma16816(acc[mt][nt], al[mt], bh[p][nh], bh[p][nh + 1]);
            }
        }
    }

    // ---- epilogue ----
    const int rowb = bm + wm * 32 + (lane >> 2);
    const int colb = bn + wn * (NT8 * 8) + 2 * (lane & 3);
#pragma unroll
    for (int mt = 0; mt < MT; mt++) {
#pragma unroll
        for (int nt = 0; nt < NT8; nt++) {
            const int col = colb + nt * 8;
            float2 b2 = make_float2(0.f, 0.f);
            if (bias) b2 = *(const float2*)(bias + col);
#pragma unroll
            for (int hh = 0; hh < 2; hh++) {
                const int row = rowb + mt * 16 + hh * 8;
                if (row >= M) continue;
                float v0 = acc[mt][nt][hh * 2 + 0] + b2.x;
                float v1 = acc[mt][nt][hh * 2 + 1] + b2.y;
                if (act == 0) {
                    *(float2*)(Cf + (size_t)row * N + col) = make_float2(v0, v1);
                } else {
                    v0 = geluf(v0); v1 = geluf(v1);
                    __nv_bfloat16 h0, l0, h1, l1;
                    splitf(v0, h0, l0);
                    splitf(v1, h1, l1);
                    *(__nv_bfloat162*)(Ch + (size_t)row * N + col) = __nv_bfloat162(h0, h1);
                    *(__nv_bfloat162*)(Cl + (size_t)row * N + col) = __nv_bfloat162(l0, l1);
                }
            }
        }
    }
}

static constexpr int MMASM128 = 4 * (2 * 128 * 24 * 2 + 2 * 64 * 24 * 2);  // 73728
static constexpr int MMASM64  = 4 * (2 * 64 * 24 * 2 + 2 * 64 * 24 * 2);   // 49152

// ---------------------------------------------------------------------------
// weight split: fp32 -> bf16 hi/lo, 17 segments
// ---------------------------------------------------------------------------
struct CSeg { const float* src; __nv_bfloat16* h; __nv_bfloat16* l; int blk_off; };
struct CTable { CSeg seg[17]; };
__global__ void __launch_bounds__(256) wsplit_kernel(CTable t)
{
    const int bt = blockIdx.x;
    int s = 0;
#pragma unroll
    for (int i = 1; i < 17; i++) if (t.seg[i].blk_off <= bt) s = i;
    const CSeg sg = t.seg[s];
    const int idx = (bt - sg.blk_off) * 1024 + threadIdx.x * 4;
    float4 v = *(const float4*)(sg.src + idx);
    __nv_bfloat16 h, l;
    splitf(v.x, h, l); sg.h[idx + 0] = h; sg.l[idx + 0] = l;
    splitf(v.y, h, l); sg.h[idx + 1] = h; sg.l[idx + 1] = l;
    splitf(v.z, h, l); sg.h[idx + 2] = h; sg.l[idx + 2] = l;
    splitf(v.w, h, l); sg.h[idx + 3] = h; sg.l[idx + 3] = l;
}

// ---------------------------------------------------------------------------
// transpose for FMA-path weights: src[N,K] -> dst[K,N]; 7 segments
// ---------------------------------------------------------------------------
struct TSeg { const float* src; float* dst; int N; int K; int tile_off; };
struct TTable { TSeg seg[7]; };
__global__ void __launch_bounds__(256) transpose_kernel(TTable t)
{
    __shared__ float sm[32][33];
    const int bt = blockIdx.x;
    int s = 0;
#pragma unroll
    for (int i = 1; i < 7; i++) if (t.seg[i].tile_off <= bt) s = i;
    const TSeg sg = t.seg[s];
    const int lt = bt - sg.tile_off;
    const int tk = sg.K >> 5;
    const int nr = (lt / tk) << 5;
    const int kc = (lt % tk) << 5;
    const int tx = threadIdx.x & 31, ty = threadIdx.x >> 5;
#pragma unroll
    for (int i = 0; i < 4; i++)
        sm[ty + i * 8][tx] = sg.src[(size_t)(nr + ty + i * 8) * sg.K + kc + tx];
    __syncthreads();
#pragma unroll
    for (int i = 0; i < 4; i++)
        sg.dst[(size_t)(kc + ty + i * 8) * sg.N + nr + tx] = sm[tx][ty + i * 8];
}

// ---------------------------------------------------------------------------
// FMA sgemm (small M)
// ---------------------------------------------------------------------------
__global__ void __launch_bounds__(256) sgemm_kernel(
    const float* __restrict__ A, const float* __restrict__ Wt,
    const float* __restrict__ bias, const float* __restrict__ R,
    float* __restrict__ C, int M, int N, int K, int act)
{
    constexpr int BM = 32, RPT = 2, S = 4;
    __shared__ __align__(16) float As[S][BM][20];
    __shared__ __align__(16) float Ws[S][16][68];
    const int tid = threadIdx.x;
    const int tx = tid & 15;
    const int ty = tid >> 4;
    const int bm = blockIdx.y * BM;
    const int bn = blockIdx.x * 64;
    const int kkW = tid >> 4;
    const int nW  = (tid & 15) << 2;
    const float* WtBase = Wt + (size_t)kkW * N + bn + nW;
    const int rA = tid >> 2;
    const int cA = (tid & 3) << 2;
    const bool a_thread = (tid < 128);
    const bool a_ok = a_thread && (bm + rA) < M;
    const float* Ap = A + (size_t)(bm + rA) * K + cA;

    unsigned int sW[S], sA[S];
#pragma unroll
    for (int s = 0; s < S; s++) {
        sW[s] = (unsigned int)__cvta_generic_to_shared(&Ws[s][kkW][nW]);
        sA[s] = (unsigned int)__cvta_generic_to_shared(&As[s][rA & (BM - 1)][cA]);
    }
    const int niter = K >> 4;
#pragma unroll
    for (int s = 0; s < S - 1; s++) {
        const int k0 = s << 4;
        cpa16(sW[s], WtBase + (size_t)k0 * N, true);
        if (a_thread) cpa16(sA[s], Ap + k0, a_ok);
        cpa_commit();
    }
    unsigned long long acc[RPT][2];
#pragma unroll
    for (int i = 0; i < RPT; i++) { acc[i][0] = 0ull; acc[i][1] = 0ull; }

    for (int it = 0; it < niter; it++) {
        cpa_waitg<2>();
        __syncthreads();
        const int nit = it + S - 1;
        if (nit < niter) {
            const int nb = nit & (S - 1);
            const int k0 = nit << 4;
            cpa16(sW[nb], WtBase + (size_t)k0 * N, true);
            if (a_thread) cpa16(sA[nb], Ap + k0, a_ok);
        }
        cpa_commit();
        const int buf = it & (S - 1);
#pragma unroll
        for (int kk = 0; kk < 16; kk++) {
            ulonglong2 bb = *(const ulonglong2*)&Ws[buf][kk][tx << 2];
#pragma unroll
            for (int i = 0; i < RPT; i++) {
                float a = As[buf][ty * RPT + i][kk];
                unsigned long long a2;
                asm("mov.b64 %0, {%1, %1};" : "=l"(a2) : "f"(a));
                fma2(acc[i][0], a2, bb.x);
                fma2(acc[i][1], a2, bb.y);
            }
        }
    }
    const int col0 = bn + (tx << 2);
    float4 b4 = make_float4(0.f, 0.f, 0.f, 0.f);
    if (bias) b4 = *(const float4*)(bias + col0);
#pragma unroll
    for (int i = 0; i < RPT; i++) {
        int row = bm + ty * RPT + i;
        if (row >= M) continue;
        float2 v0 = u2f2(acc[i][0]);
        float2 v1 = u2f2(acc[i][1]);
        float4 o;
        o.x = v0.x + b4.x; o.y = v0.y + b4.y; o.z = v1.x + b4.z; o.w = v1.y + b4.w;
        if (R) {
            float4 r4 = *(const float4*)(R + (size_t)row * N + col0);
            o.x += r4.x; o.y += r4.y; o.z += r4.z; o.w += r4.w;
        }
        if (act == 1) { o.x = geluf(o.x); o.y = geluf(o.y); o.z = geluf(o.z); o.w = geluf(o.w); }
        *(float4*)(C + (size_t)row * N + col0) = o;
    }
}

// ---------------------------------------------------------------------------
// LN (+optional vectorized bf16 hi/lo emit)
// ---------------------------------------------------------------------------
__global__ void ln_kernel(const float* __restrict__ x, const float* __restrict__ r,
                          const float* __restrict__ gg, const float* __restrict__ bb,
                          float* __restrict__ y,
                          __nv_bfloat16* __restrict__ yh, __nv_bfloat16* __restrict__ yl,
                          int rows)
{
    int gid = blockIdx.x * blockDim.x + threadIdx.x;
    int row = gid >> 5;
    int lane = gid & 31;
    if (row >= rows) return;
    const float* xp = x + (size_t)row * 256;
    float4 a = *(const float4*)(xp + lane * 4);
    float4 c = *(const float4*)(xp + 128 + lane * 4);
    if (r) {
        const float* rp = r + (size_t)row * 256;
        float4 ra = *(const float4*)(rp + lane * 4);
        float4 rc = *(const float4*)(rp + 128 + lane * 4);
        a.x += ra.x; a.y += ra.y; a.z += ra.z; a.w += ra.w;
        c.x += rc.x; c.y += rc.y; c.z += rc.z; c.w += rc.w;
    }
    float s = a.x + a.y + a.z + a.w + c.x + c.y + c.z + c.w;
    float q = a.x * a.x + a.y * a.y + a.z * a.z + a.w * a.w
            + c.x * c.x + c.y * c.y + c.z * c.z + c.w * c.w;
#pragma unroll
    for (int o = 16; o; o >>= 1) {
        s += __shfl_xor_sync(0xffffffffu, s, o);
        q += __shfl_xor_sync(0xffffffffu, q, o);
    }
    float mean = s * (1.f / 256.f);
    float var = q * (1.f / 256.f) - mean * mean;
    float rstd = rsqrtf(var + 1e-5f);
    float4 g0 = *(const float4*)(gg + lane * 4);
    float4 g1 = *(const float4*)(gg + 128 + lane * 4);
    float4 b0 = *(const float4*)(bb + lane * 4);
    float4 b1 = *(const float4*)(bb + 128 + lane * 4);
    float4 o0, o1;
    o0.x = (a.x - mean) * rstd * g0.x + b0.x;
    o0.y = (a.y - mean) * rstd * g0.y + b0.y;
    o0.z = (a.z - mean) * rstd * g0.z + b0.z;
    o0.w = (a.w - mean) * rstd * g0.w + b0.w;
    o1.x = (c.x - mean) * rstd * g1.x + b1.x;
    o1.y = (c.y - mean) * rstd * g1.y + b1.y;
    o1.z = (c.z - mean) * rstd * g1.z + b1.z;
    o1.w = (c.w - mean) * rstd * g1.w + b1.w;
    float* yp = y + (size_t)row * 256;
    *(float4*)(yp + lane * 4) = o0;
    *(float4*)(yp + 128 + lane * 4) = o1;
    if (yh) {
        const float ov[8] = {o0.x, o0.y, o0.z, o0.w, o1.x, o1.y, o1.z, o1.w};
        __nv_bfloat16 hv[8], lv[8];
#pragma unroll
        for (int i = 0; i < 8; i++) splitf(ov[i], hv[i], lv[i]);
        const size_t b0o = (size_t)row * 256 + lane * 4;
        *(__nv_bfloat162*)(yh + b0o)       = __nv_bfloat162(hv[0], hv[1]);
        *(__nv_bfloat162*)(yh + b0o + 2)   = __nv_bfloat162(hv[2], hv[3]);
        *(__nv_bfloat162*)(yh + b0o + 128) = __nv_bfloat162(hv[4], hv[5]);
        *(__nv_bfloat162*)(yh + b0o + 130) = __nv_bfloat162(hv[6], hv[7]);
        *(__nv_bfloat162*)(yl + b0o)       = __nv_bfloat162(lv[0], lv[1]);
        *(__nv_bfloat162*)(yl + b0o + 2)   = __nv_bfloat162(lv[2], lv[3]);
        *(__nv_bfloat162*)(yl + b0o + 128) = __nv_bfloat162(lv[4], lv[5]);
        *(__nv_bfloat162*)(yl + b0o + 130) = __nv_bfloat162(lv[6], lv[7]);
    }
}

__global__ void pe_kernel(const int* __restrict__ coords, const float* __restrict__ re,
                          const float* __restrict__ ce, float* __restrict__ pe)
{
    int idx = blockIdx.x * blockDim.x + threadIdx.x;
    if (idx >= B * P * D) return;
    int d = idx & 255;
    int bp = idx >> 8;
    int r = coords[bp * 2 + 0];
    int c = coords[bp * 2 + 1];
    r = min(max(r, 0), 255);
    c = min(max(c, 0), 255);
    pe[idx] = (d < 128) ? re[r * 128 + d] : ce[c * 128 + (d - 128)];
}

__global__ void qinit_kernel(const float* __restrict__ gq, float* __restrict__ q,
                             __nv_bfloat16* __restrict__ qh, __nv_bfloat16* __restrict__ ql)
{
    int idx = blockIdx.x * blockDim.x + threadIdx.x;
    if (idx >= B * G * D) return;
    float v = gq[idx % (G * D)];
    q[idx] = v;
    __nv_bfloat16 h, l;
    splitf(v, h, l);
    qh[idx] = h;
    ql[idx] = l;
}

// ---------------------------------------------------------------------------
// Cross-attention; outputs bf16 hi/lo context.
// ---------------------------------------------------------------------------
__global__ void __launch_bounds__(256) attn_kernel(
    const float* __restrict__ Q, const float* __restrict__ KV,
    __nv_bfloat16* __restrict__ cxh, __nv_bfloat16* __restrict__ cxl)
{
    __shared__ float Kt[32][196];
    const int bh = blockIdx.x;
    const int b = bh >> 3, h = bh & 7;
    const int tid = threadIdx.x;
    const int lane = tid & 31, w = tid >> 5;

    const float* KVb = KV + (size_t)b * P * 512;
    for (int i = tid; i < P * 32; i += 256) {
        int p = i >> 5, d = i & 31;
        Kt[d][p] = KVb[(size_t)p * 512 + h * 32 + d] * ATT_SCALE;
    }
    __syncthreads();

    const int g0 = (blockIdx.y * 8 + w) * 4;
    if (g0 >= G) return;

    float qr[4];
#pragma unroll
    for (int i = 0; i < 4; i++)
        qr[i] = Q[(size_t)(b * G + g0 + i) * 256 + h * 32 + lane];

    float sc[4][7];
#pragma unroll
    for (int i = 0; i < 4; i++)
#pragma unroll
        for (int j = 0; j < 7; j++) sc[i][j] = 0.f;

#pragma unroll 4
    for (int d = 0; d < 32; d++) {
        float k0 = Kt[d][lane];
        float k1 = Kt[d][32 + lane];
        float k2 = Kt[d][64 + lane];
        float k3 = Kt[d][96 + lane];
        float k4 = Kt[d][128 + lane];
        float k5 = Kt[d][160 + lane];
        float k6 = (lane < 4) ? Kt[d][192 + lane] : 0.f;
#pragma unroll
        for (int i = 0; i < 4; i++) {
            float qd = __shfl_sync(0xffffffffu, qr[i], d);
            sc[i][0] = fmaf(qd, k0, sc[i][0]);
            sc[i][1] = fmaf(qd, k1, sc[i][1]);
            sc[i][2] = fmaf(qd, k2, sc[i][2]);
            sc[i][3] = fmaf(qd, k3, sc[i][3]);
            sc[i][4] = fmaf(qd, k4, sc[i][4]);
            sc[i][5] = fmaf(qd, k5, sc[i][5]);
            sc[i][6] = fmaf(qd, k6, sc[i][6]);
        }
    }

#pragma unroll
    for (int i = 0; i < 4; i++) {
        if (lane >= 4) sc[i][6] = -1e30f;
        float m = sc[i][0];
#pragma unroll
        for (int j = 1; j < 7; j++) m = fmaxf(m, sc[i][j]);
#pragma unroll
        for (int o = 16; o; o >>= 1) m = fmaxf(m, __shfl_xor_sync(0xffffffffu, m, o));
        float s = 0.f;
#pragma unroll
        for (int j = 0; j < 7; j++) { float e = __expf(sc[i][j] - m); sc[i][j] = e; s += e; }
#pragma unroll
        for (int o = 16; o; o >>= 1) s += __shfl_xor_sync(0xffffffffu, s, o);
        float inv = 1.0f / s;
#pragma unroll
        for (int j = 0; j < 7; j++) sc[i][j] *= inv;
    }

    float cx[4] = {0.f, 0.f, 0.f, 0.f};
    const float* Vb = KVb + 256 + h * 32 + lane;
#pragma unroll
    for (int jj = 0; jj < 7; jj++) {
        const int kmax = (jj == 6) ? 4 : 32;
        for (int src = 0; src < kmax; src++) {
            float v = Vb[(size_t)(jj * 32 + src) * 512];
#pragma unroll
            for (int i = 0; i < 4; i++) {
                float a = __shfl_sync(0xffffffffu, sc[i][jj], src);
                cx[i] = fmaf(a, v, cx[i]);
            }
        }
    }
#pragma unroll
    for (int i = 0; i < 4; i++) {
        size_t off = (size_t)(b * G + g0 + i) * 256 + h * 32 + lane;
        __nv_bfloat16 hh, ll;
        splitf(cx[i], hh, ll);
        cxh[off] = hh;
        cxl[off] = ll;
    }
}

__global__ void __launch_bounds__(256) head_kernel(
    const float* __restrict__ qp, const float* __restrict__ pp, float* __restrict__ out)
{
    const int bp = blockIdx.y;
    const int b = (bp >= P) ? 1 : 0;
    const int g = blockIdx.x * 8 + (threadIdx.x >> 5);
    const int hh = (threadIdx.x & 31) << 2;
    float4 pv = *(const float4*)(pp + (size_t)bp * HALF + hh);
    float4 qv = *(const float4*)(qp + (size_t)(b * G + g) * HALF + hh);
    float4 o;
    o.x = softplusf(pv.x + qv.x);
    o.y = softplusf(pv.y + qv.y);
    o.z = softplusf(pv.z + qv.z);
    o.w = softplusf(pv.w + qv.w);
    *(float4*)(out + ((size_t)bp * G + g) * HALF + hh) = o;
}

// ---------------------------------------------------------------------------
static inline void sgemm_small(const float* A, const float* Wt, const float* bias,
                               const float* R, float* C, int M, int N, int K, int act)
{
    dim3 grid(N / 64, (M + 31) / 32);
    sgemm_kernel<<<grid, 256>>>(A, Wt, bias, R, C, M, N, K, act);
}

extern "C" void kernel_launch(void* const* d_in, const int* in_sizes, int n_in,
                              void* d_out, int out_size)
{
    (void)in_sizes; (void)n_in; (void)out_size;
    const float* patch_features = (const float*)d_in[0];
    const int*   patch_coords   = (const int*)d_in[1];
    const float* patch_proj_w   = (const float*)d_in[2];
    const float* patch_proj_b   = (const float*)d_in[3];
    const float* patch_ln_g     = (const float*)d_in[4];
    const float* patch_ln_b     = (const float*)d_in[5];
    const float* row_embed      = (const float*)d_in[6];
    const float* col_embed      = (const float*)d_in[7];
    const float* pe_proj_w      = (const float*)d_in[8];
    const float* pe_proj_b      = (const float*)d_in[9];
    const float* gene_queries   = (const float*)d_in[10];
    const float* in_proj_w      = (const float*)d_in[11];
    const float* in_proj_b      = (const float*)d_in[12];
    const float* out_w          = (const float*)d_in[13];
    const float* out_b          = (const float*)d_in[14];
    const float* ff1_w          = (const float*)d_in[15];
    const float* ff1_b          = (const float*)d_in[16];
    const float* ff2_w          = (const float*)d_in[17];
    const float* ff2_b          = (const float*)d_in[18];
    const float* ln1_g          = (const float*)d_in[19];
    const float* ln1_b          = (const float*)d_in[20];
    const float* ln2_g          = (const float*)d_in[21];
    const float* ln2_b          = (const float*)d_in[22];
    const float* head_w1        = (const float*)d_in[23];
    const float* head_b1        = (const float*)d_in[24];
    float* out = (float*)d_out;

    cudaFuncSetAttribute(mma_gemm_kernel<128>, cudaFuncAttributeMaxDynamicSharedMemorySize, MMASM128);
    cudaFuncSetAttribute(mma_gemm_kernel<64>,  cudaFuncAttributeMaxDynamicSharedMemorySize, MMASM64);

    float* ws = nullptr;
    cudaGetSymbolAddress((void**)&ws, g_ws);
    __nv_bfloat16* bf = nullptr;
    cudaGetSymbolAddress((void**)&bf, g_bf);

    float* patch_emb = ws + OFF_PATCH;
    float* tmp       = ws + OFF_TMP;
    float* pe        = ws + OFF_PE;
    float* kv        = ws + OFF_KV;
    float* q         = ws + OFF_Q;
    float* Qb        = ws + OFF_QB;
    float* att       = ws + OFF_ATT;
    float* qproj     = ws + OFF_QP;
    float* pproj     = ws + OFF_PP;
    float* wtPatch   = ws + OFF_WT_PATCH;
    float* wtPe      = ws + OFF_WT_PE;
    float* wtWkv     = ws + OFF_WT_WKV;
    float* wtHead    = ws + OFF_WT_HEAD;

    __nv_bfloat16* qh  = bf + BF_QH;
    __nv_bfloat16* ql  = bf + BF_QL;
    __nv_bfloat16* l1h = bf + BF_L1H;
    __nv_bfloat16* l1l = bf + BF_L1L;
    __nv_bfloat16* cxh = bf + BF_CXH;
    __nv_bfloat16* cxl = bf + BF_CXL;
    __nv_bfloat16* fh  = bf + BF_FH;
    __nv_bfloat16* fl  = bf + BF_FL;

    // ---- one-time weight prep ----
    TTable tt;
    {
        int seg = 0, toff = 0;
        auto add = [&](const float* src, float* dst, int N, int K) {
            tt.seg[seg] = { src, dst, N, K, toff };
            toff += (N >> 5) * (K >> 5);
            seg++;
        };
        add(patch_proj_w, wtPatch, 256, 1024);
        add(pe_proj_w,    wtPe,    256, 256);
        for (int l = 0; l < NL; l++)
            add(in_proj_w + (size_t)l * 3 * D * D + D * D, wtWkv + (size_t)l * 512 * 256, 512, 256);
        add(head_w1, wtHead, 128, 256);
        transpose_kernel<<<toff, 256>>>(tt);
    }
    CTable ct;
    {
        int seg = 0, boff = 0;
        auto add = [&](const float* src, size_t ho, size_t lo, int count) {
            ct.seg[seg] = { src, bf + ho, bf + lo, boff };
            boff += count / 1024;
            seg++;
        };
        for (int l = 0; l < NL; l++)
            add(in_proj_w + (size_t)l * 3 * D * D, BF_WQH + (size_t)l * D * D, BF_WQL + (size_t)l * D * D, D * D);
        for (int l = 0; l < NL; l++)
            add(out_w + (size_t)l * D * D, BF_WOH + (size_t)l * D * D, BF_WOL + (size_t)l * D * D, D * D);
        for (int l = 0; l < NL; l++)
            add(ff1_w + (size_t)l * 4 * D * D, BF_F1H + (size_t)l * 4 * D * D, BF_F1L + (size_t)l * 4 * D * D, 4 * D * D);
        for (int l = 0; l < NL; l++)
            add(ff2_w + (size_t)l * 4 * D * D, BF_F2H + (size_t)l * 4 * D * D, BF_F2L + (size_t)l * 4 * D * D, 4 * D * D);
        add(head_w1, BF_HDH, BF_HDL, HALF * D);
        int total = ct.seg[16].blk_off + (HALF * D) / 1024;
        wsplit_kernel<<<total, 256>>>(ct);
    }

    // ---- Stage A ----
    sgemm_small(patch_features, wtPatch, patch_proj_b, nullptr, tmp, MP, D, FD, 0);
    ln_kernel<<<(MP + 7) / 8, 256>>>(tmp, nullptr, patch_ln_g, patch_ln_b, patch_emb,
                                     nullptr, nullptr, MP);
    pe_kernel<<<(B * P * D + 255) / 256, 256>>>(patch_coords, row_embed, col_embed, pe);
    sgemm_small(pe, wtPe, pe_proj_b, patch_emb, patch_emb, MP, D, D, 0);
    qinit_kernel<<<(MQ * D + 255) / 256, 256>>>(gene_queries, q, qh, ql);

    const int MT64  = (MQ + 63) / 64;     // 63
    const int MT128 = (MQ + 127) / 128;   // 32
    // ---- Stage B: decoder layers ----
    for (int l = 0; l < NL; l++) {
        const float* bq  = in_proj_b + (size_t)l * 3 * D;
        const float* bkv = bq + D;
        mma_gemm_kernel<64><<<dim3(D / 64, MT64), 256, MMASM64>>>(
            qh, ql, bf + BF_WQH + (size_t)l * D * D, bf + BF_WQL + (size_t)l * D * D,
            bq, Qb, nullptr, nullptr, MQ, D, D, 0);
        sgemm_small(patch_emb, wtWkv + (size_t)l * 512 * 256, bkv, nullptr, kv, MP, 2 * D, D, 0);
        attn_kernel<<<dim3(B * H, (G + 31) / 32), 256>>>(Qb, kv, cxh, cxl);
        mma_gemm_kernel<64><<<dim3(D / 64, MT64), 256, MMASM64>>>(
            cxh, cxl, bf + BF_WOH + (size_t)l * D * D, bf + BF_WOL + (size_t)l * D * D,
            out_b + (size_t)l * D, att, nullptr, nullptr, MQ, D, D, 0);
        ln_kernel<<<(MQ + 7) / 8, 256>>>(q, att, ln1_g + (size_t)l * D, ln1_b + (size_t)l * D,
                                         q, l1h, l1l, MQ);
        mma_gemm_kernel<128><<<dim3(4 * D / 64, MT128), 256, MMASM128>>>(
            l1h, l1l, bf + BF_F1H + (size_t)l * 4 * D * D, bf + BF_F1L + (size_t)l * 4 * D * D,
            ff1_b + (size_t)l * 4 * D, nullptr, fh, fl, MQ, 4 * D, D, 1);
        mma_gemm_kernel<64><<<dim3(D / 64, MT64), 256, MMASM64>>>(
            fh, fl, bf + BF_F2H + (size_t)l * 4 * D * D, bf + BF_F2L + (size_t)l * 4 * D * D,
            ff2_b + (size_t)l * D, att, nullptr, nullptr, MQ, D, 4 * D, 0);
        ln_kernel<<<(MQ + 7) / 8, 256>>>(q, att, ln2_g + (size_t)l * D, ln2_b + (size_t)l * D,
                                         q, qh, ql, MQ);
    }

    // ---- Stage C ----
    mma_gemm_kernel<64><<<dim3(HALF / 64, MT64), 256, MMASM64>>>(
        qh, ql, bf + BF_HDH, bf + BF_HDL, head_b1, qproj, nullptr, nullptr, MQ, HALF, D, 0);
    sgemm_small(patch_emb, wtHead, nullptr, nullptr, pproj, MP, HALF, D, 0);
    head_kernel<<<dim3(G / 8, B * P), 256>>>(qproj, pproj, out);
}

// round 8
// speedup vs baseline: 1.0568x; 1.0568x over previous
#include <cuda_runtime.h>
#include <cuda_bf16.h>
#include <cstddef>
#include <cstdint>
#include <math.h>

// ---------------------------------------------------------------------------
// SpatialTranscriptomicsDecoder — GB300 sm_103a. Round 8.
// ALL GEMMs via mma.sync bf16x2-split (3-term comp), 4-stage cp.async pipeline.
// fp32 FMA path removed; small-M GEMMs converted; residual fused into mma.
// ---------------------------------------------------------------------------

static constexpr int B = 2, P = 196, FD = 1024, G = 2000, D = 256, H = 8, NL = 4, HALF = 128;
static constexpr float ATT_SCALE = 0.17677669529663687f;
static constexpr int MQ = B * G;   // 4000
static constexpr int MP = B * P;   // 392

// ---------------- fp32 workspace ----------------
static constexpr size_t OFF_PATCH = 0;
static constexpr size_t OFF_TMP   = OFF_PATCH + (size_t)MP * D;
static constexpr size_t OFF_KV    = OFF_TMP   + (size_t)MP * D;
static constexpr size_t OFF_Q     = OFF_KV    + (size_t)MP * 2 * D;
static constexpr size_t OFF_QB    = OFF_Q     + (size_t)MQ * D;
static constexpr size_t OFF_ATT   = OFF_QB    + (size_t)MQ * D;
static constexpr size_t OFF_QP    = OFF_ATT   + (size_t)MQ * D;
static constexpr size_t OFF_PP    = OFF_QP    + (size_t)MQ * HALF;
static constexpr size_t WS_TOTAL  = OFF_PP    + (size_t)MP * HALF;
__device__ float g_ws[WS_TOTAL];

// ---------------- bf16 workspace ----------------
static constexpr size_t BQ  = (size_t)MQ * D;
static constexpr size_t BF_QH  = 0;
static constexpr size_t BF_QL  = BF_QH + BQ;
static constexpr size_t BF_L1H = BF_QL + BQ;
static constexpr size_t BF_L1L = BF_L1H + BQ;
static constexpr size_t BF_CXH = BF_L1L + BQ;
static constexpr size_t BF_CXL = BF_CXH + BQ;
static constexpr size_t BF_FH  = BF_CXL + BQ;
static constexpr size_t BF_FL  = BF_FH + (size_t)MQ * 4 * D;
static constexpr size_t BF_WQH = BF_FL + (size_t)MQ * 4 * D;
static constexpr size_t BF_WQL = BF_WQH + (size_t)NL * D * D;
static constexpr size_t BF_WOH = BF_WQL + (size_t)NL * D * D;
static constexpr size_t BF_WOL = BF_WOH + (size_t)NL * D * D;
static constexpr size_t BF_F1H = BF_WOL + (size_t)NL * D * D;
static constexpr size_t BF_F1L = BF_F1H + (size_t)NL * 4 * D * D;
static constexpr size_t BF_F2H = BF_F1L + (size_t)NL * 4 * D * D;
static constexpr size_t BF_F2L = BF_F2H + (size_t)NL * 4 * D * D;
static constexpr size_t BF_HDH = BF_F2L + (size_t)NL * 4 * D * D;
static constexpr size_t BF_HDL = BF_HDH + (size_t)HALF * D;
// new: patch pipeline bf16 buffers/weights
static constexpr size_t BF_PFH = BF_HDL + (size_t)HALF * D;
static constexpr size_t BF_PFL = BF_PFH + (size_t)MP * FD;
static constexpr size_t BF_PEH = BF_PFL + (size_t)MP * FD;
static constexpr size_t BF_PEL = BF_PEH + (size_t)MP * D;
static constexpr size_t BF_PCH = BF_PEL + (size_t)MP * D;
static constexpr size_t BF_PCL = BF_PCH + (size_t)MP * D;
static constexpr size_t BF_WPH = BF_PCL + (size_t)MP * D;
static constexpr size_t BF_WPL = BF_WPH + (size_t)D * FD;
static constexpr size_t BF_WEH = BF_WPL + (size_t)D * FD;
static constexpr size_t BF_WEL = BF_WEH + (size_t)D * D;
static constexpr size_t BF_WKH = BF_WEL + (size_t)D * D;
static constexpr size_t BF_WKL = BF_WKH + (size_t)NL * 2 * D * D;
static constexpr size_t BF_TOTAL = BF_WKL + (size_t)NL * 2 * D * D;
__device__ __nv_bfloat16 g_bf[BF_TOTAL];

// ---------------- helpers ----------------
__device__ __forceinline__ float geluf(float x) {
    return 0.5f * x * (1.0f + erff(x * 0.7071067811865476f));
}
__device__ __forceinline__ float softplusf(float x) {
    return fmaxf(x, 0.0f) + __logf(1.0f + __expf(-fabsf(x)));
}
__device__ __forceinline__ void splitf(float v, __nv_bfloat16& h, __nv_bfloat16& l) {
    h = __float2bfloat16(v);
    l = __float2bfloat16(v - __bfloat162float(h));
}
__device__ __forceinline__ void cpa16(unsigned int dst, const void* src, bool ok) {
    asm volatile("cp.async.ca.shared.global [%0], [%1], 16, %2;"
                 :: "r"(dst), "l"(src), "r"(ok ? 16 : 0) : "memory");
}
__device__ __forceinline__ void cpa_commit() {
    asm volatile("cp.async.commit_group;" ::: "memory");
}
template<int Ng> __device__ __forceinline__ void cpa_waitg() {
    asm volatile("cp.async.wait_group %0;" :: "n"(Ng) : "memory");
}
__device__ __forceinline__ void ldm4(unsigned& r0, unsigned& r1, unsigned& r2, unsigned& r3,
                                     unsigned addr) {
    asm volatile("ldmatrix.sync.aligned.m8n8.x4.shared.b16 {%0,%1,%2,%3}, [%4];"
                 : "=r"(r0), "=r"(r1), "=r"(r2), "=r"(r3) : "r"(addr));
}
__device__ __forceinline__ void mma16816(float* d, const unsigned* a, unsigned b0, unsigned b1) {
    asm volatile(
        "mma.sync.aligned.m16n8k16.row.col.f32.bf16.bf16.f32 "
        "{%0,%1,%2,%3}, {%4,%5,%6,%7}, {%8,%9}, {%0,%1,%2,%3};"
        : "+f"(d[0]), "+f"(d[1]), "+f"(d[2]), "+f"(d[3])
        : "r"(a[0]), "r"(a[1]), "r"(a[2]), "r"(a[3]), "r"(b0), "r"(b1));
}

// ---------------------------------------------------------------------------
// mma.sync GEMM: C[M,N] = act( (Ah+Al) @ (Wh+Wl)^T + bias + R ); 3-term comp.
// grid (N/64, ceil(M/BM)), 256 threads. 4-stage cp.async pipeline.
// Epilogue: optional fp32 out Cf, optional residual R, optional split out Ch/Cl.
// ---------------------------------------------------------------------------
template<int BM>
__global__ void __launch_bounds__(256) mma_gemm_kernel(
    const __nv_bfloat16* __restrict__ Ah, const __nv_bfloat16* __restrict__ Al,
    const __nv_bfloat16* __restrict__ Wh, const __nv_bfloat16* __restrict__ Wl,
    const float* __restrict__ bias, const float* __restrict__ R,
    float* __restrict__ Cf, __nv_bfloat16* __restrict__ Ch, __nv_bfloat16* __restrict__ Cl,
    int M, int N, int K, int act)
{
    constexpr int STR = 24;                       // bf16 per smem row (48B)
    constexpr int szA = BM * STR * 2;
    constexpr int szW = 64 * STR * 2;
    constexpr int STG = 2 * szA + 2 * szW;
    constexpr int MT  = 2;
    constexpr int WMASK  = (BM == 128) ? 3 : 1;
    constexpr int WSHIFT = (BM == 128) ? 2 : 1;
    constexpr int NT8 = (BM == 128) ? 4 : 2;
    constexpr int NP  = NT8 / 2;
    constexpr int NLD = (BM == 128) ? 3 : 2;

    extern __shared__ char smem[];
    const unsigned sb = (unsigned)__cvta_generic_to_shared(smem);

    const int tid = threadIdx.x;
    const int lane = tid & 31, wid = tid >> 5;
    const int wm = wid & WMASK, wn = wid >> WSHIFT;
    const int bm = blockIdx.y * BM;
    const int bn = blockIdx.x * 64;
    const int NC = K >> 4;

    // ---- per-thread load descriptors ----
    unsigned off[NLD];
    const __nv_bfloat16* src[NLD];
    bool okf[NLD];
    if (BM == 128) {
        const int rowA = tid >> 1, segA = tid & 1;
        const bool aok = (bm + rowA) < M;
        off[0] = (unsigned)((rowA * STR + segA * 8) * 2);
        src[0] = Ah + (size_t)(bm + rowA) * K + segA * 8; okf[0] = aok;
        off[1] = (unsigned)(szA + (rowA * STR + segA * 8) * 2);
        src[1] = Al + (size_t)(bm + rowA) * K + segA * 8; okf[1] = aok;
        const int rowW = (tid & 127) >> 1, segW = tid & 1;
        off[NLD - 1] = (unsigned)(2 * szA + (tid < 128 ? 0 : szW) + (rowW * STR + segW * 8) * 2);
        src[NLD - 1] = (tid < 128 ? Wh : Wl) + (size_t)(bn + rowW) * K + segW * 8;
        okf[NLD - 1] = true;
    } else {
        const int rowA = (tid & 127) >> 1, segA = tid & 1;
        const bool aok = (bm + rowA) < M;
        off[0] = (unsigned)((tid < 128 ? 0 : szA) + (rowA * STR + segA * 8) * 2);
        src[0] = (tid < 128 ? Ah : Al) + (size_t)(bm + rowA) * K + segA * 8; okf[0] = aok;
        off[1] = (unsigned)(2 * szA + (tid < 128 ? 0 : szW) + (rowA * STR + segA * 8) * 2);
        src[1] = (tid < 128 ? Wh : Wl) + (size_t)(bn + rowA) * K + segA * 8; okf[1] = true;
    }

    auto loadChunk = [&](int kc, int s) {
        const int o = kc << 4;
        const unsigned base = sb + s * STG;
#pragma unroll
        for (int i = 0; i < NLD; i++) cpa16(base + off[i], src[i] + o, okf[i]);
        cpa_commit();
    };

    // ---- ldmatrix within-stage offsets ----
    unsigned aoffH[MT], boffH[NP];
    {
        const int ar = wm * 32 + (lane & 15);
        const int ak = (lane >> 4) * 8;
        const int br = wn * (NT8 * 8) + (lane & 7) + ((lane >> 4) << 3);
        const int bk = ((lane >> 3) & 1) * 8;
#pragma unroll
        for (int t = 0; t < MT; t++) aoffH[t] = (unsigned)(((ar + t * 16) * STR + ak) * 2);
#pragma unroll
        for (int p = 0; p < NP; p++) boffH[p] = (unsigned)(2 * szA + ((br + p * 16) * STR + bk) * 2);
    }

    loadChunk(0, 0);
    loadChunk(1, 1);
    loadChunk(2, 2);

    float acc[MT][NT8][4];
#pragma unroll
    for (int i = 0; i < MT; i++)
#pragma unroll
        for (int j = 0; j < NT8; j++)
#pragma unroll
            for (int k = 0; k < 4; k++) acc[i][j][k] = 0.f;

    for (int kc = 0; kc < NC; kc++) {
        cpa_waitg<2>();
        __syncthreads();
        const int s = kc & 3;
        const int nk = kc + 3;
        if (nk < NC) loadChunk(nk, nk & 3);
        else cpa_commit();

        const unsigned stg = sb + s * STG;
        unsigned ah[MT][4], al[MT][4], bh[NP][4], bl[NP][4];
#pragma unroll
        for (int t = 0; t < MT; t++) {
            ldm4(ah[t][0], ah[t][1], ah[t][2], ah[t][3], stg + aoffH[t]);
            ldm4(al[t][0], al[t][1], al[t][2], al[t][3], stg + aoffH[t] + szA);
        }
#pragma unroll
        for (int p = 0; p < NP; p++) {
            ldm4(bh[p][0], bh[p][1], bh[p][2], bh[p][3], stg + boffH[p]);
            ldm4(bl[p][0], bl[p][1], bl[p][2], bl[p][3], stg + boffH[p] + szW);
        }
#pragma unroll
        for (int mt = 0; mt < MT; mt++) {
#pragma unroll
            for (int nt = 0; nt < NT8; nt++) {
                const int p = nt >> 1, nh = (nt & 1) << 1;
                mma16816(acc[mt][nt], ah[mt], bh[p][nh], bh[p][nh + 1]);
                mma16816(acc[mt][nt], ah[mt], bl[p][nh], bl[p][nh + 1]);
                mma16816(acc[mt][nt], al[mt], bh[p][nh], bh[p][nh + 1]);
            }
        }
    }

    // ---- epilogue ----
    const int rowb = bm + wm * 32 + (lane >> 2);
    const int colb = bn + wn * (NT8 * 8) + 2 * (lane & 3);
#pragma unroll
    for (int mt = 0; mt < MT; mt++) {
#pragma unroll
        for (int nt = 0; nt < NT8; nt++) {
            const int col = colb + nt * 8;
            float2 b2 = make_float2(0.f, 0.f);
            if (bias) b2 = *(const float2*)(bias + col);
#pragma unroll
            for (int hh = 0; hh < 2; hh++) {
                const int row = rowb + mt * 16 + hh * 8;
                if (row >= M) continue;
                float v0 = acc[mt][nt][hh * 2 + 0] + b2.x;
                float v1 = acc[mt][nt][hh * 2 + 1] + b2.y;
                if (R) {
                    float2 r2 = *(const float2*)(R + (size_t)row * N + col);
                    v0 += r2.x; v1 += r2.y;
                }
                if (act == 1) { v0 = geluf(v0); v1 = geluf(v1); }
                if (Cf) *(float2*)(Cf + (size_t)row * N + col) = make_float2(v0, v1);
                if (Ch) {
                    __nv_bfloat16 h0, l0, h1, l1;
                    splitf(v0, h0, l0);
                    splitf(v1, h1, l1);
                    *(__nv_bfloat162*)(Ch + (size_t)row * N + col) = __nv_bfloat162(h0, h1);
                    *(__nv_bfloat162*)(Cl + (size_t)row * N + col) = __nv_bfloat162(l0, l1);
                }
            }
        }
    }
}

static constexpr int MMASM128 = 4 * (2 * 128 * 24 * 2 + 2 * 64 * 24 * 2);  // 73728
static constexpr int MMASM64  = 4 * (2 * 64 * 24 * 2 + 2 * 64 * 24 * 2);   // 49152

// ---------------------------------------------------------------------------
// weight split: fp32 -> bf16 hi/lo, 23 segments, 1024 elems/block
// ---------------------------------------------------------------------------
struct CSeg { const float* src; __nv_bfloat16* h; __nv_bfloat16* l; int blk_off; };
struct CTable { CSeg seg[23]; };
__global__ void __launch_bounds__(256) wsplit_kernel(CTable t)
{
    const int bt = blockIdx.x;
    int s = 0;
#pragma unroll
    for (int i = 1; i < 23; i++) if (t.seg[i].blk_off <= bt) s = i;
    const CSeg sg = t.seg[s];
    const int idx = (bt - sg.blk_off) * 1024 + threadIdx.x * 4;
    float4 v = *(const float4*)(sg.src + idx);
    __nv_bfloat16 h, l;
    splitf(v.x, h, l); sg.h[idx + 0] = h; sg.l[idx + 0] = l;
    splitf(v.y, h, l); sg.h[idx + 1] = h; sg.l[idx + 1] = l;
    splitf(v.z, h, l); sg.h[idx + 2] = h; sg.l[idx + 2] = l;
    splitf(v.w, h, l); sg.h[idx + 3] = h; sg.l[idx + 3] = l;
}

// activation split: fp32 -> bf16 hi/lo (patch_features)
__global__ void __launch_bounds__(256) asplit_kernel(
    const float* __restrict__ src, __nv_bfloat16* __restrict__ h,
    __nv_bfloat16* __restrict__ l, int n)
{
    int idx = (blockIdx.x * 256 + threadIdx.x) * 4;
    if (idx >= n) return;
    float4 v = *(const float4*)(src + idx);
    __nv_bfloat16 hh, ll;
    splitf(v.x, hh, ll); h[idx + 0] = hh; l[idx + 0] = ll;
    splitf(v.y, hh, ll); h[idx + 1] = hh; l[idx + 1] = ll;
    splitf(v.z, hh, ll); h[idx + 2] = hh; l[idx + 2] = ll;
    splitf(v.w, hh, ll); h[idx + 3] = hh; l[idx + 3] = ll;
}

// ---------------------------------------------------------------------------
// LN (+optional vectorized bf16 hi/lo emit)
// ---------------------------------------------------------------------------
__global__ void ln_kernel(const float* __restrict__ x, const float* __restrict__ r,
                          const float* __restrict__ gg, const float* __restrict__ bb,
                          float* __restrict__ y,
                          __nv_bfloat16* __restrict__ yh, __nv_bfloat16* __restrict__ yl,
                          int rows)
{
    int gid = blockIdx.x * blockDim.x + threadIdx.x;
    int row = gid >> 5;
    int lane = gid & 31;
    if (row >= rows) return;
    const float* xp = x + (size_t)row * 256;
    float4 a = *(const float4*)(xp + lane * 4);
    float4 c = *(const float4*)(xp + 128 + lane * 4);
    if (r) {
        const float* rp = r + (size_t)row * 256;
        float4 ra = *(const float4*)(rp + lane * 4);
        float4 rc = *(const float4*)(rp + 128 + lane * 4);
        a.x += ra.x; a.y += ra.y; a.z += ra.z; a.w += ra.w;
        c.x += rc.x; c.y += rc.y; c.z += rc.z; c.w += rc.w;
    }
    float s = a.x + a.y + a.z + a.w + c.x + c.y + c.z + c.w;
    float q = a.x * a.x + a.y * a.y + a.z * a.z + a.w * a.w
            + c.x * c.x + c.y * c.y + c.z * c.z + c.w * c.w;
#pragma unroll
    for (int o = 16; o; o >>= 1) {
        s += __shfl_xor_sync(0xffffffffu, s, o);
        q += __shfl_xor_sync(0xffffffffu, q, o);
    }
    float mean = s * (1.f / 256.f);
    float var = q * (1.f / 256.f) - mean * mean;
    float rstd = rsqrtf(var + 1e-5f);
    float4 g0 = *(const float4*)(gg + lane * 4);
    float4 g1 = *(const float4*)(gg + 128 + lane * 4);
    float4 b0 = *(const float4*)(bb + lane * 4);
    float4 b1 = *(const float4*)(bb + 128 + lane * 4);
    float4 o0, o1;
    o0.x = (a.x - mean) * rstd * g0.x + b0.x;
    o0.y = (a.y - mean) * rstd * g0.y + b0.y;
    o0.z = (a.z - mean) * rstd * g0.z + b0.z;
    o0.w = (a.w - mean) * rstd * g0.w + b0.w;
    o1.x = (c.x - mean) * rstd * g1.x + b1.x;
    o1.y = (c.y - mean) * rstd * g1.y + b1.y;
    o1.z = (c.z - mean) * rstd * g1.z + b1.z;
    o1.w = (c.w - mean) * rstd * g1.w + b1.w;
    float* yp = y + (size_t)row * 256;
    *(float4*)(yp + lane * 4) = o0;
    *(float4*)(yp + 128 + lane * 4) = o1;
    if (yh) {
        const float ov[8] = {o0.x, o0.y, o0.z, o0.w, o1.x, o1.y, o1.z, o1.w};
        __nv_bfloat16 hv[8], lv[8];
#pragma unroll
        for (int i = 0; i < 8; i++) splitf(ov[i], hv[i], lv[i]);
        const size_t b0o = (size_t)row * 256 + lane * 4;
        *(__nv_bfloat162*)(yh + b0o)       = __nv_bfloat162(hv[0], hv[1]);
        *(__nv_bfloat162*)(yh + b0o + 2)   = __nv_bfloat162(hv[2], hv[3]);
        *(__nv_bfloat162*)(yh + b0o + 128) = __nv_bfloat162(hv[4], hv[5]);
        *(__nv_bfloat162*)(yh + b0o + 130) = __nv_bfloat162(hv[6], hv[7]);
        *(__nv_bfloat162*)(yl + b0o)       = __nv_bfloat162(lv[0], lv[1]);
        *(__nv_bfloat162*)(yl + b0o + 2)   = __nv_bfloat162(lv[2], lv[3]);
        *(__nv_bfloat162*)(yl + b0o + 128) = __nv_bfloat162(lv[4], lv[5]);
        *(__nv_bfloat162*)(yl + b0o + 130) = __nv_bfloat162(lv[6], lv[7]);
    }
}

// pe gather -> bf16 hi/lo directly
__global__ void pe_kernel(const int* __restrict__ coords, const float* __restrict__ re,
                          const float* __restrict__ ce,
                          __nv_bfloat16* __restrict__ peh, __nv_bfloat16* __restrict__ pel)
{
    int idx = blockIdx.x * blockDim.x + threadIdx.x;
    if (idx >= B * P * D) return;
    int d = idx & 255;
    int bp = idx >> 8;
    int r = coords[bp * 2 + 0];
    int c = coords[bp * 2 + 1];
    r = min(max(r, 0), 255);
    c = min(max(c, 0), 255);
    float v = (d < 128) ? re[r * 128 + d] : ce[c * 128 + (d - 128)];
    __nv_bfloat16 h, l;
    splitf(v, h, l);
    peh[idx] = h;
    pel[idx] = l;
}

__global__ void qinit_kernel(const float* __restrict__ gq, float* __restrict__ q,
                             __nv_bfloat16* __restrict__ qh, __nv_bfloat16* __restrict__ ql)
{
    int idx = blockIdx.x * blockDim.x + threadIdx.x;
    if (idx >= B * G * D) return;
    float v = gq[idx % (G * D)];
    q[idx] = v;
    __nv_bfloat16 h, l;
    splitf(v, h, l);
    qh[idx] = h;
    ql[idx] = l;
}

// ---------------------------------------------------------------------------
// Cross-attention; outputs bf16 hi/lo context.
// ---------------------------------------------------------------------------
__global__ void __launch_bounds__(256) attn_kernel(
    const float* __restrict__ Q, const float* __restrict__ KV,
    __nv_bfloat16* __restrict__ cxh, __nv_bfloat16* __restrict__ cxl)
{
    __shared__ float Kt[32][196];
    const int bh = blockIdx.x;
    const int b = bh >> 3, h = bh & 7;
    const int tid = threadIdx.x;
    const int lane = tid & 31, w = tid >> 5;

    const float* KVb = KV + (size_t)b * P * 512;
    for (int i = tid; i < P * 32; i += 256) {
        int p = i >> 5, d = i & 31;
        Kt[d][p] = KVb[(size_t)p * 512 + h * 32 + d] * ATT_SCALE;
    }
    __syncthreads();

    const int g0 = (blockIdx.y * 8 + w) * 4;
    if (g0 >= G) return;

    float qr[4];
#pragma unroll
    for (int i = 0; i < 4; i++)
        qr[i] = Q[(size_t)(b * G + g0 + i) * 256 + h * 32 + lane];

    float sc[4][7];
#pragma unroll
    for (int i = 0; i < 4; i++)
#pragma unroll
        for (int j = 0; j < 7; j++) sc[i][j] = 0.f;

#pragma unroll 4
    for (int d = 0; d < 32; d++) {
        float k0 = Kt[d][lane];
        float k1 = Kt[d][32 + lane];
        float k2 = Kt[d][64 + lane];
        float k3 = Kt[d][96 + lane];
        float k4 = Kt[d][128 + lane];
        float k5 = Kt[d][160 + lane];
        float k6 = (lane < 4) ? Kt[d][192 + lane] : 0.f;
#pragma unroll
        for (int i = 0; i < 4; i++) {
            float qd = __shfl_sync(0xffffffffu, qr[i], d);
            sc[i][0] = fmaf(qd, k0, sc[i][0]);
            sc[i][1] = fmaf(qd, k1, sc[i][1]);
            sc[i][2] = fmaf(qd, k2, sc[i][2]);
            sc[i][3] = fmaf(qd, k3, sc[i][3]);
            sc[i][4] = fmaf(qd, k4, sc[i][4]);
            sc[i][5] = fmaf(qd, k5, sc[i][5]);
            sc[i][6] = fmaf(qd, k6, sc[i][6]);
        }
    }

#pragma unroll
    for (int i = 0; i < 4; i++) {
        if (lane >= 4) sc[i][6] = -1e30f;
        float m = sc[i][0];
#pragma unroll
        for (int j = 1; j < 7; j++) m = fmaxf(m, sc[i][j]);
#pragma unroll
        for (int o = 16; o; o >>= 1) m = fmaxf(m, __shfl_xor_sync(0xffffffffu, m, o));
        float s = 0.f;
#pragma unroll
        for (int j = 0; j < 7; j++) { float e = __expf(sc[i][j] - m); sc[i][j] = e; s += e; }
#pragma unroll
        for (int o = 16; o; o >>= 1) s += __shfl_xor_sync(0xffffffffu, s, o);
        float inv = 1.0f / s;
#pragma unroll
        for (int j = 0; j < 7; j++) sc[i][j] *= inv;
    }

    float cx[4] = {0.f, 0.f, 0.f, 0.f};
    const float* Vb = KVb + 256 + h * 32 + lane;
#pragma unroll
    for (int jj = 0; jj < 7; jj++) {
        const int kmax = (jj == 6) ? 4 : 32;
        for (int src = 0; src < kmax; src++) {
            float v = Vb[(size_t)(jj * 32 + src) * 512];
#pragma unroll
            for (int i = 0; i < 4; i++) {
                float a = __shfl_sync(0xffffffffu, sc[i][jj], src);
                cx[i] = fmaf(a, v, cx[i]);
            }
        }
    }
#pragma unroll
    for (int i = 0; i < 4; i++) {
        size_t off = (size_t)(b * G + g0 + i) * 256 + h * 32 + lane;
        __nv_bfloat16 hh, ll;
        splitf(cx[i], hh, ll);
        cxh[off] = hh;
        cxl[off] = ll;
    }
}

__global__ void __launch_bounds__(256) head_kernel(
    const float* __restrict__ qp, const float* __restrict__ pp, float* __restrict__ out)
{
    const int bp = blockIdx.y;
    const int b = (bp >= P) ? 1 : 0;
    const int g = blockIdx.x * 8 + (threadIdx.x >> 5);
    const int hh = (threadIdx.x & 31) << 2;
    float4 pv = *(const float4*)(pp + (size_t)bp * HALF + hh);
    float4 qv = *(const float4*)(qp + (size_t)(b * G + g) * HALF + hh);
    float4 o;
    o.x = softplusf(pv.x + qv.x);
    o.y = softplusf(pv.y + qv.y);
    o.z = softplusf(pv.z + qv.z);
    o.w = softplusf(pv.w + qv.w);
    *(float4*)(out + ((size_t)bp * G + g) * HALF + hh) = o;
}

// ---------------------------------------------------------------------------
extern "C" void kernel_launch(void* const* d_in, const int* in_sizes, int n_in,
                              void* d_out, int out_size)
{
    (void)in_sizes; (void)n_in; (void)out_size;
    const float* patch_features = (const float*)d_in[0];
    const int*   patch_coords   = (const int*)d_in[1];
    const float* patch_proj_w   = (const float*)d_in[2];
    const float* patch_proj_b   = (const float*)d_in[3];
    const float* patch_ln_g     = (const float*)d_in[4];
    const float* patch_ln_b     = (const float*)d_in[5];
    const float* row_embed      = (const float*)d_in[6];
    const float* col_embed      = (const float*)d_in[7];
    const float* pe_proj_w      = (const float*)d_in[8];
    const float* pe_proj_b      = (const float*)d_in[9];
    const float* gene_queries   = (const float*)d_in[10];
    const float* in_proj_w      = (const float*)d_in[11];
    const float* in_proj_b      = (const float*)d_in[12];
    const float* out_w          = (const float*)d_in[13];
    const float* out_b          = (const float*)d_in[14];
    const float* ff1_w          = (const float*)d_in[15];
    const float* ff1_b          = (const float*)d_in[16];
    const float* ff2_w          = (const float*)d_in[17];
    const float* ff2_b          = (const float*)d_in[18];
    const float* ln1_g          = (const float*)d_in[19];
    const float* ln1_b          = (const float*)d_in[20];
    const float* ln2_g          = (const float*)d_in[21];
    const float* ln2_b          = (const float*)d_in[22];
    const float* head_w1        = (const float*)d_in[23];
    const float* head_b1        = (const float*)d_in[24];
    float* out = (float*)d_out;

    cudaFuncSetAttribute(mma_gemm_kernel<128>, cudaFuncAttributeMaxDynamicSharedMemorySize, MMASM128);
    cudaFuncSetAttribute(mma_gemm_kernel<64>,  cudaFuncAttributeMaxDynamicSharedMemorySize, MMASM64);

    float* ws = nullptr;
    cudaGetSymbolAddress((void**)&ws, g_ws);
    __nv_bfloat16* bf = nullptr;
    cudaGetSymbolAddress((void**)&bf, g_bf);

    float* patch_emb = ws + OFF_PATCH;
    float* tmp       = ws + OFF_TMP;
    float* kv        = ws + OFF_KV;
    float* q         = ws + OFF_Q;
    float* Qb        = ws + OFF_QB;
    float* att       = ws + OFF_ATT;
    float* qproj     = ws + OFF_QP;
    float* pproj     = ws + OFF_PP;

    __nv_bfloat16* qh  = bf + BF_QH;
    __nv_bfloat16* ql  = bf + BF_QL;
    __nv_bfloat16* l1h = bf + BF_L1H;
    __nv_bfloat16* l1l = bf + BF_L1L;
    __nv_bfloat16* cxh = bf + BF_CXH;
    __nv_bfloat16* cxl = bf + BF_CXL;
    __nv_bfloat16* fh  = bf + BF_FH;
    __nv_bfloat16* fl  = bf + BF_FL;
    __nv_bfloat16* pfh = bf + BF_PFH;
    __nv_bfloat16* pfl = bf + BF_PFL;
    __nv_bfloat16* peh = bf + BF_PEH;
    __nv_bfloat16* pel = bf + BF_PEL;
    __nv_bfloat16* pch = bf + BF_PCH;
    __nv_bfloat16* pcl = bf + BF_PCL;

    // ---- one-time weight split (23 segments) ----
    CTable ct;
    int total_blk;
    {
        int seg = 0, boff = 0;
        auto add = [&](const float* src, size_t ho, size_t lo, int count) {
            ct.seg[seg] = { src, bf + ho, bf + lo, boff };
            boff += count / 1024;
            seg++;
        };
        for (int l = 0; l < NL; l++)
            add(in_proj_w + (size_t)l * 3 * D * D, BF_WQH + (size_t)l * D * D, BF_WQL + (size_t)l * D * D, D * D);
        for (int l = 0; l < NL; l++)
            add(out_w + (size_t)l * D * D, BF_WOH + (size_t)l * D * D, BF_WOL + (size_t)l * D * D, D * D);
        for (int l = 0; l < NL; l++)
            add(ff1_w + (size_t)l * 4 * D * D, BF_F1H + (size_t)l * 4 * D * D, BF_F1L + (size_t)l * 4 * D * D, 4 * D * D);
        for (int l = 0; l < NL; l++)
            add(ff2_w + (size_t)l * 4 * D * D, BF_F2H + (size_t)l * 4 * D * D, BF_F2L + (size_t)l * 4 * D * D, 4 * D * D);
        add(head_w1, BF_HDH, BF_HDL, HALF * D);
        add(patch_proj_w, BF_WPH, BF_WPL, D * FD);
        add(pe_proj_w, BF_WEH, BF_WEL, D * D);
        for (int l = 0; l < NL; l++)
            add(in_proj_w + (size_t)l * 3 * D * D + D * D,
                BF_WKH + (size_t)l * 2 * D * D, BF_WKL + (size_t)l * 2 * D * D, 2 * D * D);
        total_blk = boff;
    }
    wsplit_kernel<<<total_blk, 256>>>(ct);
    asplit_kernel<<<(MP * FD / 4 + 255) / 256, 256>>>(patch_features, pfh, pfl, MP * FD);

    const int MT64  = (MQ + 63) / 64;     // 63
    const int MT128 = (MQ + 127) / 128;   // 32
    const int MTP   = (MP + 63) / 64;     // 7

    // ---- Stage A: patch embedding (all mma) ----
    mma_gemm_kernel<64><<<dim3(D / 64, MTP), 256, MMASM64>>>(
        pfh, pfl, bf + BF_WPH, bf + BF_WPL, patch_proj_b, nullptr,
        tmp, nullptr, nullptr, MP, D, FD, 0);
    ln_kernel<<<(MP + 7) / 8, 256>>>(tmp, nullptr, patch_ln_g, patch_ln_b, patch_emb,
                                     nullptr, nullptr, MP);
    pe_kernel<<<(B * P * D + 255) / 256, 256>>>(patch_coords, row_embed, col_embed, peh, pel);
    // patch_emb = pe@Wpe + b + patch_emb; also emit hi/lo for kv/pproj consumers
    mma_gemm_kernel<64><<<dim3(D / 64, MTP), 256, MMASM64>>>(
        peh, pel, bf + BF_WEH, bf + BF_WEL, pe_proj_b, patch_emb,
        nullptr, pch, pcl, MP, D, D, 0);
    qinit_kernel<<<(MQ * D + 255) / 256, 256>>>(gene_queries, q, qh, ql);

    // ---- Stage B: decoder layers ----
    for (int l = 0; l < NL; l++) {
        const float* bq  = in_proj_b + (size_t)l * 3 * D;
        const float* bkv = bq + D;
        mma_gemm_kernel<64><<<dim3(D / 64, MT64), 256, MMASM64>>>(
            qh, ql, bf + BF_WQH + (size_t)l * D * D, bf + BF_WQL + (size_t)l * D * D,
            bq, nullptr, Qb, nullptr, nullptr, MQ, D, D, 0);
        mma_gemm_kernel<64><<<dim3(2 * D / 64, MTP), 256, MMASM64>>>(
            pch, pcl, bf + BF_WKH + (size_t)l * 2 * D * D, bf + BF_WKL + (size_t)l * 2 * D * D,
            bkv, nullptr, kv, nullptr, nullptr, MP, 2 * D, D, 0);
        attn_kernel<<<dim3(B * H, (G + 31) / 32), 256>>>(Qb, kv, cxh, cxl);
        mma_gemm_kernel<64><<<dim3(D / 64, MT64), 256, MMASM64>>>(
            cxh, cxl, bf + BF_WOH + (size_t)l * D * D, bf + BF_WOL + (size_t)l * D * D,
            out_b + (size_t)l * D, nullptr, att, nullptr, nullptr, MQ, D, D, 0);
        ln_kernel<<<(MQ + 7) / 8, 256>>>(q, att, ln1_g + (size_t)l * D, ln1_b + (size_t)l * D,
                                         q, l1h, l1l, MQ);
        mma_gemm_kernel<128><<<dim3(4 * D / 64, MT128), 256, MMASM128>>>(
            l1h, l1l, bf + BF_F1H + (size_t)l * 4 * D * D, bf + BF_F1L + (size_t)l * 4 * D * D,
            ff1_b + (size_t)l * 4 * D, nullptr, nullptr, fh, fl, MQ, 4 * D, D, 1);
        mma_gemm_kernel<64><<<dim3(D / 64, MT64), 256, MMASM64>>>(
            fh, fl, bf + BF_F2H + (size_t)l * 4 * D * D, bf + BF_F2L + (size_t)l * 4 * D * D,
            ff2_b + (size_t)l * D, nullptr, att, nullptr, nullptr, MQ, D, 4 * D, 0);
        ln_kernel<<<(MQ + 7) / 8, 256>>>(q, att, ln2_g + (size_t)l * D, ln2_b + (size_t)l * D,
                                         q, qh, ql, MQ);
    }

    // ---- Stage C ----
    mma_gemm_kernel<64><<<dim3(HALF / 64, MT64), 256, MMASM64>>>(
        qh, ql, bf + BF_HDH, bf + BF_HDL, head_b1, nullptr,
        qproj, nullptr, nullptr, MQ, HALF, D, 0);
    mma_gemm_kernel<64><<<dim3(HALF / 64, MTP), 256, MMASM64>>>(
        pch, pcl, bf + BF_HDH, bf + BF_HDL, nullptr, nullptr,
        pproj, nullptr, nullptr, MP, HALF, D, 0);
    head_kernel<<<dim3(G / 8, B * P), 256>>>(qproj, pproj, out);
}

// round 9
// speedup vs baseline: 1.1819x; 1.1184x over previous
#include <cuda_runtime.h>
#include <cuda_fp16.h>
#include <cstddef>
#include <cstdint>
#include <math.h>

// ---------------------------------------------------------------------------
// SpatialTranscriptomicsDecoder — GB300 sm_103a. Round 9.
// All GEMMs: mma.sync fp16 2-term split (A=Ah+Al, B=Bh): C = Ah*Bh + Al*Bh.
// 4-stage cp.async pipeline, BM={128,64}. Error ~1e-4 << 1e-3 threshold.
// ---------------------------------------------------------------------------

static constexpr int B = 2, P = 196, FD = 1024, G = 2000, D = 256, H = 8, NL = 4, HALF = 128;
static constexpr float ATT_SCALE = 0.17677669529663687f;
static constexpr int MQ = B * G;   // 4000
static constexpr int MP = B * P;   // 392

// ---------------- fp32 workspace ----------------
static constexpr size_t OFF_PATCH = 0;
static constexpr size_t OFF_TMP   = OFF_PATCH + (size_t)MP * D;
static constexpr size_t OFF_KV    = OFF_TMP   + (size_t)MP * D;
static constexpr size_t OFF_Q     = OFF_KV    + (size_t)MP * 2 * D;
static constexpr size_t OFF_QB    = OFF_Q     + (size_t)MQ * D;
static constexpr size_t OFF_ATT   = OFF_QB    + (size_t)MQ * D;
static constexpr size_t OFF_QP    = OFF_ATT   + (size_t)MQ * D;
static constexpr size_t OFF_PP    = OFF_QP    + (size_t)MQ * HALF;
static constexpr size_t WS_TOTAL  = OFF_PP    + (size_t)MP * HALF;
__device__ float g_ws[WS_TOTAL];

// ---------------- fp16 workspace ----------------
static constexpr size_t BQ  = (size_t)MQ * D;
static constexpr size_t HF_QH  = 0;
static constexpr size_t HF_QL  = HF_QH + BQ;
static constexpr size_t HF_L1H = HF_QL + BQ;
static constexpr size_t HF_L1L = HF_L1H + BQ;
static constexpr size_t HF_CXH = HF_L1L + BQ;
static constexpr size_t HF_CXL = HF_CXH + BQ;
static constexpr size_t HF_FH  = HF_CXL + BQ;
static constexpr size_t HF_FL  = HF_FH + (size_t)MQ * 4 * D;
static constexpr size_t HF_PFH = HF_FL + (size_t)MQ * 4 * D;
static constexpr size_t HF_PFL = HF_PFH + (size_t)MP * FD;
static constexpr size_t HF_PEH = HF_PFL + (size_t)MP * FD;
static constexpr size_t HF_PEL = HF_PEH + (size_t)MP * D;
static constexpr size_t HF_PCH = HF_PEL + (size_t)MP * D;
static constexpr size_t HF_PCL = HF_PCH + (size_t)MP * D;
// weights: fp16 hi only
static constexpr size_t HF_WQ  = HF_PCL + (size_t)MP * D;
static constexpr size_t HF_WO  = HF_WQ  + (size_t)NL * D * D;
static constexpr size_t HF_F1  = HF_WO  + (size_t)NL * D * D;
static constexpr size_t HF_F2  = HF_F1  + (size_t)NL * 4 * D * D;
static constexpr size_t HF_HD  = HF_F2  + (size_t)NL * 4 * D * D;
static constexpr size_t HF_WP  = HF_HD  + (size_t)HALF * D;
static constexpr size_t HF_WE  = HF_WP  + (size_t)D * FD;
static constexpr size_t HF_WK  = HF_WE  + (size_t)D * D;
static constexpr size_t HF_TOTAL = HF_WK + (size_t)NL * 2 * D * D;
__device__ __half g_hf[HF_TOTAL];

// ---------------- helpers ----------------
__device__ __forceinline__ float geluf(float x) {
    return 0.5f * x * (1.0f + erff(x * 0.7071067811865476f));
}
__device__ __forceinline__ float softplusf(float x) {
    return fmaxf(x, 0.0f) + __logf(1.0f + __expf(-fabsf(x)));
}
__device__ __forceinline__ void splith(float v, __half& h, __half& l) {
    h = __float2half_rn(v);
    l = __float2half_rn(v - __half2float(h));
}
__device__ __forceinline__ void cpa16(unsigned int dst, const void* src, bool ok) {
    asm volatile("cp.async.ca.shared.global [%0], [%1], 16, %2;"
                 :: "r"(dst), "l"(src), "r"(ok ? 16 : 0) : "memory");
}
__device__ __forceinline__ void cpa_commit() {
    asm volatile("cp.async.commit_group;" ::: "memory");
}
template<int Ng> __device__ __forceinline__ void cpa_waitg() {
    asm volatile("cp.async.wait_group %0;" :: "n"(Ng) : "memory");
}
__device__ __forceinline__ void ldm4(unsigned& r0, unsigned& r1, unsigned& r2, unsigned& r3,
                                     unsigned addr) {
    asm volatile("ldmatrix.sync.aligned.m8n8.x4.shared.b16 {%0,%1,%2,%3}, [%4];"
                 : "=r"(r0), "=r"(r1), "=r"(r2), "=r"(r3) : "r"(addr));
}
__device__ __forceinline__ void mma16816(float* d, const unsigned* a, unsigned b0, unsigned b1) {
    asm volatile(
        "mma.sync.aligned.m16n8k16.row.col.f32.f16.f16.f32 "
        "{%0,%1,%2,%3}, {%4,%5,%6,%7}, {%8,%9}, {%0,%1,%2,%3};"
        : "+f"(d[0]), "+f"(d[1]), "+f"(d[2]), "+f"(d[3])
        : "r"(a[0]), "r"(a[1]), "r"(a[2]), "r"(a[3]), "r"(b0), "r"(b1));
}

// ---------------------------------------------------------------------------
// mma GEMM: C[M,N] = act( (Ah+Al) @ Bh^T + bias + R )   (B pre-rounded fp16)
// grid (N/64, ceil(M/BM)), 256 threads, 4-stage cp.async pipeline.
// Epilogue: optional fp32 Cf, optional residual R, optional split out Ch/Cl.
// ---------------------------------------------------------------------------
template<int BM>
__global__ void __launch_bounds__(256) mma_gemm_kernel(
    const __half* __restrict__ Ah, const __half* __restrict__ Al,
    const __half* __restrict__ Wh,
    const float* __restrict__ bias, const float* __restrict__ R,
    float* __restrict__ Cf, __half* __restrict__ Ch, __half* __restrict__ Cl,
    int M, int N, int K, int act)
{
    constexpr int STR = 24;                      // halfs per smem row (48B)
    constexpr int szA = BM * STR * 2;            // bytes per A matrix per stage
    constexpr int szW = 64 * STR * 2;
    constexpr int STG = 2 * szA + szW;
    constexpr int MT  = 2;
    constexpr int WMASK  = (BM == 128) ? 3 : 1;
    constexpr int WSHIFT = (BM == 128) ? 2 : 1;
    constexpr int NT8 = (BM == 128) ? 4 : 2;
    constexpr int NP  = NT8 / 2;

    extern __shared__ char smem[];
    const unsigned sb = (unsigned)__cvta_generic_to_shared(smem);

    const int tid = threadIdx.x;
    const int lane = tid & 31, wid = tid >> 5;
    const int wm = wid & WMASK, wn = wid >> WSHIFT;
    const int bm = blockIdx.y * BM;
    const int bn = blockIdx.x * 64;
    const int NC = K >> 4;

    // ---- per-thread load descriptors ----
    // BM=128: all threads: Ah+Al at rowA=tid>>1; tid<128 also W at rowW=tid>>1.
    // BM=64 : tid<128: Ah+Al at rowA=tid>>1; tid>=128: W at rowW=(tid-128)>>1.
    unsigned offA = 0, offW = 0;
    const __half* srcA = nullptr;
    const __half* srcW = nullptr;
    bool aok = false, doA = false, doW = false;
    if (BM == 128) {
        const int rowA = tid >> 1, segA = tid & 1;
        doA = true;
        aok = (bm + rowA) < M;
        offA = (unsigned)((rowA * STR + segA * 8) * 2);
        srcA = (const __half*)((size_t)(bm + rowA) * K + segA * 8 + (size_t)0);  // placeholder
        srcA = Ah + (size_t)(bm + rowA) * K + segA * 8;
        if (tid < 128) {
            const int rowW = tid >> 1, segW = tid & 1;
            doW = true;
            offW = (unsigned)(2 * szA + (rowW * STR + segW * 8) * 2);
            srcW = Wh + (size_t)(bn + rowW) * K + segW * 8;
        }
    } else {
        if (tid < 128) {
            const int rowA = tid >> 1, segA = tid & 1;
            doA = true;
            aok = (bm + rowA) < M;
            offA = (unsigned)((rowA * STR + segA * 8) * 2);
            srcA = Ah + (size_t)(bm + rowA) * K + segA * 8;
        } else {
            const int rowW = (tid - 128) >> 1, segW = tid & 1;
            doW = true;
            offW = (unsigned)(2 * szA + (rowW * STR + segW * 8) * 2);
            srcW = Wh + (size_t)(bn + rowW) * K + segW * 8;
        }
    }
    const ptrdiff_t alDelta = Al - Ah;   // same layout for Al

    auto loadChunk = [&](int kc, int s) {
        const int o = kc << 4;
        const unsigned base = sb + s * STG;
        if (doA) {
            cpa16(base + offA, srcA + o, aok);
            cpa16(base + szA + offA, srcA + alDelta + o, aok);
        }
        if (doW) cpa16(base + offW, srcW + o, true);
        cpa_commit();
    };

    // ---- ldmatrix within-stage offsets ----
    unsigned aoffH[MT], boffH[NP];
    {
        const int ar = wm * 32 + (lane & 15);
        const int ak = (lane >> 4) * 8;
        const int br = wn * (NT8 * 8) + (lane & 7) + ((lane >> 4) << 3);
        const int bk = ((lane >> 3) & 1) * 8;
#pragma unroll
        for (int t = 0; t < MT; t++) aoffH[t] = (unsigned)(((ar + t * 16) * STR + ak) * 2);
#pragma unroll
        for (int p = 0; p < NP; p++) boffH[p] = (unsigned)(2 * szA + ((br + p * 16) * STR + bk) * 2);
    }

    loadChunk(0, 0);
    loadChunk(1, 1);
    loadChunk(2, 2);

    float acc[MT][NT8][4];
#pragma unroll
    for (int i = 0; i < MT; i++)
#pragma unroll
        for (int j = 0; j < NT8; j++)
#pragma unroll
            for (int k = 0; k < 4; k++) acc[i][j][k] = 0.f;

    for (int kc = 0; kc < NC; kc++) {
        cpa_waitg<2>();
        __syncthreads();
        const int s = kc & 3;
        const int nk = kc + 3;
        if (nk < NC) loadChunk(nk, nk & 3);
        else cpa_commit();

        const unsigned stg = sb + s * STG;
        unsigned ah[MT][4], al[MT][4], bh[NP][4];
#pragma unroll
        for (int t = 0; t < MT; t++) {
            ldm4(ah[t][0], ah[t][1], ah[t][2], ah[t][3], stg + aoffH[t]);
            ldm4(al[t][0], al[t][1], al[t][2], al[t][3], stg + aoffH[t] + szA);
        }
#pragma unroll
        for (int p = 0; p < NP; p++)
            ldm4(bh[p][0], bh[p][1], bh[p][2], bh[p][3], stg + boffH[p]);
#pragma unroll
        for (int mt = 0; mt < MT; mt++) {
#pragma unroll
            for (int nt = 0; nt < NT8; nt++) {
                const int p = nt >> 1, nh = (nt & 1) << 1;
                mma16816(acc[mt][nt], ah[mt], bh[p][nh], bh[p][nh + 1]);
                mma16816(acc[mt][nt], al[mt], bh[p][nh], bh[p][nh + 1]);
            }
        }
    }

    // ---- epilogue ----
    const int rowb = bm + wm * 32 + (lane >> 2);
    const int colb = bn + wn * (NT8 * 8) + 2 * (lane & 3);
#pragma unroll
    for (int mt = 0; mt < MT; mt++) {
#pragma unroll
        for (int nt = 0; nt < NT8; nt++) {
            const int col = colb + nt * 8;
            float2 b2 = make_float2(0.f, 0.f);
            if (bias) b2 = *(const float2*)(bias + col);
#pragma unroll
            for (int hh = 0; hh < 2; hh++) {
                const int row = rowb + mt * 16 + hh * 8;
                if (row >= M) continue;
                float v0 = acc[mt][nt][hh * 2 + 0] + b2.x;
                float v1 = acc[mt][nt][hh * 2 + 1] + b2.y;
                if (R) {
                    float2 r2 = *(const float2*)(R + (size_t)row * N + col);
                    v0 += r2.x; v1 += r2.y;
                }
                if (act == 1) { v0 = geluf(v0); v1 = geluf(v1); }
                if (Cf) *(float2*)(Cf + (size_t)row * N + col) = make_float2(v0, v1);
                if (Ch) {
                    __half h0, l0, h1, l1;
                    splith(v0, h0, l0);
                    splith(v1, h1, l1);
                    *(__half2*)(Ch + (size_t)row * N + col) = __halves2half2(h0, h1);
                    *(__half2*)(Cl + (size_t)row * N + col) = __halves2half2(l0, l1);
                }
            }
        }
    }
}

static constexpr int MMASM128 = 4 * (2 * 128 * 24 * 2 + 64 * 24 * 2);  // 61440
static constexpr int MMASM64  = 4 * (2 * 64 * 24 * 2 + 64 * 24 * 2);   // 36864

// ---------------------------------------------------------------------------
// weight convert: fp32 -> fp16 (hi only), 23 segments, 1024 elems/block
// ---------------------------------------------------------------------------
struct CSeg { const float* src; __half* h; int blk_off; };
struct CTable { CSeg seg[23]; };
__global__ void __launch_bounds__(256) wconv_kernel(CTable t)
{
    const int bt = blockIdx.x;
    int s = 0;
#pragma unroll
    for (int i = 1; i < 23; i++) if (t.seg[i].blk_off <= bt) s = i;
    const CSeg sg = t.seg[s];
    const int idx = (bt - sg.blk_off) * 1024 + threadIdx.x * 4;
    float4 v = *(const float4*)(sg.src + idx);
    __half2 a = __halves2half2(__float2half_rn(v.x), __float2half_rn(v.y));
    __half2 b = __halves2half2(__float2half_rn(v.z), __float2half_rn(v.w));
    *(__half2*)(sg.h + idx) = a;
    *(__half2*)(sg.h + idx + 2) = b;
}

// activation split: fp32 -> fp16 hi/lo (patch_features)
__global__ void __launch_bounds__(256) asplit_kernel(
    const float* __restrict__ src, __half* __restrict__ h,
    __half* __restrict__ l, int n)
{
    int idx = (blockIdx.x * 256 + threadIdx.x) * 4;
    if (idx >= n) return;
    float4 v = *(const float4*)(src + idx);
    __half hh, ll;
    splith(v.x, hh, ll); h[idx + 0] = hh; l[idx + 0] = ll;
    splith(v.y, hh, ll); h[idx + 1] = hh; l[idx + 1] = ll;
    splith(v.z, hh, ll); h[idx + 2] = hh; l[idx + 2] = ll;
    splith(v.w, hh, ll); h[idx + 3] = hh; l[idx + 3] = ll;
}

// ---------------------------------------------------------------------------
// LN (+optional vectorized fp16 hi/lo emit)
// ---------------------------------------------------------------------------
__global__ void ln_kernel(const float* __restrict__ x, const float* __restrict__ r,
                          const float* __restrict__ gg, const float* __restrict__ bb,
                          float* __restrict__ y,
                          __half* __restrict__ yh, __half* __restrict__ yl,
                          int rows)
{
    int gid = blockIdx.x * blockDim.x + threadIdx.x;
    int row = gid >> 5;
    int lane = gid & 31;
    if (row >= rows) return;
    const float* xp = x + (size_t)row * 256;
    float4 a = *(const float4*)(xp + lane * 4);
    float4 c = *(const float4*)(xp + 128 + lane * 4);
    if (r) {
        const float* rp = r + (size_t)row * 256;
        float4 ra = *(const float4*)(rp + lane * 4);
        float4 rc = *(const float4*)(rp + 128 + lane * 4);
        a.x += ra.x; a.y += ra.y; a.z += ra.z; a.w += ra.w;
        c.x += rc.x; c.y += rc.y; c.z += rc.z; c.w += rc.w;
    }
    float s = a.x + a.y + a.z + a.w + c.x + c.y + c.z + c.w;
    float q = a.x * a.x + a.y * a.y + a.z * a.z + a.w * a.w
            + c.x * c.x + c.y * c.y + c.z * c.z + c.w * c.w;
#pragma unroll
    for (int o = 16; o; o >>= 1) {
        s += __shfl_xor_sync(0xffffffffu, s, o);
        q += __shfl_xor_sync(0xffffffffu, q, o);
    }
    float mean = s * (1.f / 256.f);
    float var = q * (1.f / 256.f) - mean * mean;
    float rstd = rsqrtf(var + 1e-5f);
    float4 g0 = *(const float4*)(gg + lane * 4);
    float4 g1 = *(const float4*)(gg + 128 + lane * 4);
    float4 b0 = *(const float4*)(bb + lane * 4);
    float4 b1 = *(const float4*)(bb + 128 + lane * 4);
    float4 o0, o1;
    o0.x = (a.x - mean) * rstd * g0.x + b0.x;
    o0.y = (a.y - mean) * rstd * g0.y + b0.y;
    o0.z = (a.z - mean) * rstd * g0.z + b0.z;
    o0.w = (a.w - mean) * rstd * g0.w + b0.w;
    o1.x = (c.x - mean) * rstd * g1.x + b1.x;
    o1.y = (c.y - mean) * rstd * g1.y + b1.y;
    o1.z = (c.z - mean) * rstd * g1.z + b1.z;
    o1.w = (c.w - mean) * rstd * g1.w + b1.w;
    float* yp = y + (size_t)row * 256;
    *(float4*)(yp + lane * 4) = o0;
    *(float4*)(yp + 128 + lane * 4) = o1;
    if (yh) {
        const float ov[8] = {o0.x, o0.y, o0.z, o0.w, o1.x, o1.y, o1.z, o1.w};
        __half hv[8], lv[8];
#pragma unroll
        for (int i = 0; i < 8; i++) splith(ov[i], hv[i], lv[i]);
        const size_t b0o = (size_t)row * 256 + lane * 4;
        *(__half2*)(yh + b0o)       = __halves2half2(hv[0], hv[1]);
        *(__half2*)(yh + b0o + 2)   = __halves2half2(hv[2], hv[3]);
        *(__half2*)(yh + b0o + 128) = __halves2half2(hv[4], hv[5]);
        *(__half2*)(yh + b0o + 130) = __halves2half2(hv[6], hv[7]);
        *(__half2*)(yl + b0o)       = __halves2half2(lv[0], lv[1]);
        *(__half2*)(yl + b0o + 2)   = __halves2half2(lv[2], lv[3]);
        *(__half2*)(yl + b0o + 128) = __halves2half2(lv[4], lv[5]);
        *(__half2*)(yl + b0o + 130) = __halves2half2(lv[6], lv[7]);
    }
}

// pe gather -> fp16 hi/lo directly
__global__ void pe_kernel(const int* __restrict__ coords, const float* __restrict__ re,
                          const float* __restrict__ ce,
                          __half* __restrict__ peh, __half* __restrict__ pel)
{
    int idx = blockIdx.x * blockDim.x + threadIdx.x;
    if (idx >= B * P * D) return;
    int d = idx & 255;
    int bp = idx >> 8;
    int r = coords[bp * 2 + 0];
    int c = coords[bp * 2 + 1];
    r = min(max(r, 0), 255);
    c = min(max(c, 0), 255);
    float v = (d < 128) ? re[r * 128 + d] : ce[c * 128 + (d - 128)];
    __half h, l;
    splith(v, h, l);
    peh[idx] = h;
    pel[idx] = l;
}

__global__ void qinit_kernel(const float* __restrict__ gq, float* __restrict__ q,
                             __half* __restrict__ qh, __half* __restrict__ ql)
{
    int idx = blockIdx.x * blockDim.x + threadIdx.x;
    if (idx >= B * G * D) return;
    float v = gq[idx % (G * D)];
    q[idx] = v;
    __half h, l;
    splith(v, h, l);
    qh[idx] = h;
    ql[idx] = l;
}

// ---------------------------------------------------------------------------
// Cross-attention; outputs fp16 hi/lo context.
// ---------------------------------------------------------------------------
__global__ void __launch_bounds__(256) attn_kernel(
    const float* __restrict__ Q, const float* __restrict__ KV,
    __half* __restrict__ cxh, __half* __restrict__ cxl)
{
    __shared__ float Kt[32][196];
    const int bh = blockIdx.x;
    const int b = bh >> 3, h = bh & 7;
    const int tid = threadIdx.x;
    const int lane = tid & 31, w = tid >> 5;

    const float* KVb = KV + (size_t)b * P * 512;
    for (int i = tid; i < P * 32; i += 256) {
        int p = i >> 5, d = i & 31;
        Kt[d][p] = KVb[(size_t)p * 512 + h * 32 + d] * ATT_SCALE;
    }
    __syncthreads();

    const int g0 = (blockIdx.y * 8 + w) * 4;
    if (g0 >= G) return;

    float qr[4];
#pragma unroll
    for (int i = 0; i < 4; i++)
        qr[i] = Q[(size_t)(b * G + g0 + i) * 256 + h * 32 + lane];

    float sc[4][7];
#pragma unroll
    for (int i = 0; i < 4; i++)
#pragma unroll
        for (int j = 0; j < 7; j++) sc[i][j] = 0.f;

#pragma unroll 4
    for (int d = 0; d < 32; d++) {
        float k0 = Kt[d][lane];
        float k1 = Kt[d][32 + lane];
        float k2 = Kt[d][64 + lane];
        float k3 = Kt[d][96 + lane];
        float k4 = Kt[d][128 + lane];
        float k5 = Kt[d][160 + lane];
        float k6 = (lane < 4) ? Kt[d][192 + lane] : 0.f;
#pragma unroll
        for (int i = 0; i < 4; i++) {
            float qd = __shfl_sync(0xffffffffu, qr[i], d);
            sc[i][0] = fmaf(qd, k0, sc[i][0]);
            sc[i][1] = fmaf(qd, k1, sc[i][1]);
            sc[i][2] = fmaf(qd, k2, sc[i][2]);
            sc[i][3] = fmaf(qd, k3, sc[i][3]);
            sc[i][4] = fmaf(qd, k4, sc[i][4]);
            sc[i][5] = fmaf(qd, k5, sc[i][5]);
            sc[i][6] = fmaf(qd, k6, sc[i][6]);
        }
    }

#pragma unroll
    for (int i = 0; i < 4; i++) {
        if (lane >= 4) sc[i][6] = -1e30f;
        float m = sc[i][0];
#pragma unroll
        for (int j = 1; j < 7; j++) m = fmaxf(m, sc[i][j]);
#pragma unroll
        for (int o = 16; o; o >>= 1) m = fmaxf(m, __shfl_xor_sync(0xffffffffu, m, o));
        float s = 0.f;
#pragma unroll
        for (int j = 0; j < 7; j++) { float e = __expf(sc[i][j] - m); sc[i][j] = e; s += e; }
#pragma unroll
        for (int o = 16; o; o >>= 1) s += __shfl_xor_sync(0xffffffffu, s, o);
        float inv = 1.0f / s;
#pragma unroll
        for (int j = 0; j < 7; j++) sc[i][j] *= inv;
    }

    float cx[4] = {0.f, 0.f, 0.f, 0.f};
    const float* Vb = KVb + 256 + h * 32 + lane;
#pragma unroll
    for (int jj = 0; jj < 7; jj++) {
        const int kmax = (jj == 6) ? 4 : 32;
        for (int src = 0; src < kmax; src++) {
            float v = Vb[(size_t)(jj * 32 + src) * 512];
#pragma unroll
            for (int i = 0; i < 4; i++) {
                float a = __shfl_sync(0xffffffffu, sc[i][jj], src);
                cx[i] = fmaf(a, v, cx[i]);
            }
        }
    }
#pragma unroll
    for (int i = 0; i < 4; i++) {
        size_t off = (size_t)(b * G + g0 + i) * 256 + h * 32 + lane;
        __half hh, ll;
        splith(cx[i], hh, ll);
        cxh[off] = hh;
        cxl[off] = ll;
    }
}

__global__ void __launch_bounds__(256) head_kernel(
    const float* __restrict__ qp, const float* __restrict__ pp, float* __restrict__ out)
{
    const int bp = blockIdx.y;
    const int b = (bp >= P) ? 1 : 0;
    const int g = blockIdx.x * 8 + (threadIdx.x >> 5);
    const int hh = (threadIdx.x & 31) << 2;
    float4 pv = *(const float4*)(pp + (size_t)bp * HALF + hh);
    float4 qv = *(const float4*)(qp + (size_t)(b * G + g) * HALF + hh);
    float4 o;
    o.x = softplusf(pv.x + qv.x);
    o.y = softplusf(pv.y + qv.y);
    o.z = softplusf(pv.z + qv.z);
    o.w = softplusf(pv.w + qv.w);
    *(float4*)(out + ((size_t)bp * G + g) * HALF + hh) = o;
}

// ---------------------------------------------------------------------------
extern "C" void kernel_launch(void* const* d_in, const int* in_sizes, int n_in,
                              void* d_out, int out_size)
{
    (void)in_sizes; (void)n_in; (void)out_size;
    const float* patch_features = (const float*)d_in[0];
    const int*   patch_coords   = (const int*)d_in[1];
    const float* patch_proj_w   = (const float*)d_in[2];
    const float* patch_proj_b   = (const float*)d_in[3];
    const float* patch_ln_g     = (const float*)d_in[4];
    const float* patch_ln_b     = (const float*)d_in[5];
    const float* row_embed      = (const float*)d_in[6];
    const float* col_embed      = (const float*)d_in[7];
    const float* pe_proj_w      = (const float*)d_in[8];
    const float* pe_proj_b      = (const float*)d_in[9];
    const float* gene_queries   = (const float*)d_in[10];
    const float* in_proj_w      = (const float*)d_in[11];
    const float* in_proj_b      = (const float*)d_in[12];
    const float* out_w          = (const float*)d_in[13];
    const float* out_b          = (const float*)d_in[14];
    const float* ff1_w          = (const float*)d_in[15];
    const float* ff1_b          = (const float*)d_in[16];
    const float* ff2_w          = (const float*)d_in[17];
    const float* ff2_b          = (const float*)d_in[18];
    const float* ln1_g          = (const float*)d_in[19];
    const float* ln1_b          = (const float*)d_in[20];
    const float* ln2_g          = (const float*)d_in[21];
    const float* ln2_b          = (const float*)d_in[22];
    const float* head_w1        = (const float*)d_in[23];
    const float* head_b1        = (const float*)d_in[24];
    float* out = (float*)d_out;

    cudaFuncSetAttribute(mma_gemm_kernel<128>, cudaFuncAttributeMaxDynamicSharedMemorySize, MMASM128);
    cudaFuncSetAttribute(mma_gemm_kernel<64>,  cudaFuncAttributeMaxDynamicSharedMemorySize, MMASM64);

    float* ws = nullptr;
    cudaGetSymbolAddress((void**)&ws, g_ws);
    __half* hf = nullptr;
    cudaGetSymbolAddress((void**)&hf, g_hf);

    float* patch_emb = ws + OFF_PATCH;
    float* tmp       = ws + OFF_TMP;
    float* kv        = ws + OFF_KV;
    float* q         = ws + OFF_Q;
    float* Qb        = ws + OFF_QB;
    float* att       = ws + OFF_ATT;
    float* qproj     = ws + OFF_QP;
    float* pproj     = ws + OFF_PP;

    __half* qh  = hf + HF_QH;
    __half* ql  = hf + HF_QL;
    __half* l1h = hf + HF_L1H;
    __half* l1l = hf + HF_L1L;
    __half* cxh = hf + HF_CXH;
    __half* cxl = hf + HF_CXL;
    __half* fh  = hf + HF_FH;
    __half* fl  = hf + HF_FL;
    __half* pfh = hf + HF_PFH;
    __half* pfl = hf + HF_PFL;
    __half* peh = hf + HF_PEH;
    __half* pel = hf + HF_PEL;
    __half* pch = hf + HF_PCH;
    __half* pcl = hf + HF_PCL;

    // ---- one-time weight convert (23 segments, fp16 hi only) ----
    CTable ct;
    int total_blk;
    {
        int seg = 0, boff = 0;
        auto add = [&](const float* src, size_t ho, int count) {
            ct.seg[seg] = { src, hf + ho, boff };
            boff += count / 1024;
            seg++;
        };
        for (int l = 0; l < NL; l++)
            add(in_proj_w + (size_t)l * 3 * D * D, HF_WQ + (size_t)l * D * D, D * D);
        for (int l = 0; l < NL; l++)
            add(out_w + (size_t)l * D * D, HF_WO + (size_t)l * D * D, D * D);
        for (int l = 0; l < NL; l++)
            add(ff1_w + (size_t)l * 4 * D * D, HF_F1 + (size_t)l * 4 * D * D, 4 * D * D);
        for (int l = 0; l < NL; l++)
            add(ff2_w + (size_t)l * 4 * D * D, HF_F2 + (size_t)l * 4 * D * D, 4 * D * D);
        add(head_w1, HF_HD, HALF * D);
        add(patch_proj_w, HF_WP, D * FD);
        add(pe_proj_w, HF_WE, D * D);
        for (int l = 0; l < NL; l++)
            add(in_proj_w + (size_t)l * 3 * D * D + D * D, HF_WK + (size_t)l * 2 * D * D, 2 * D * D);
        total_blk = boff;
    }
    wconv_kernel<<<total_blk, 256>>>(ct);
    asplit_kernel<<<(MP * FD / 4 + 255) / 256, 256>>>(patch_features, pfh, pfl, MP * FD);

    const int MT64  = (MQ + 63) / 64;     // 63
    const int MT128 = (MQ + 127) / 128;   // 32
    const int MTP   = (MP + 63) / 64;     // 7

    // ---- Stage A: patch embedding ----
    mma_gemm_kernel<64><<<dim3(D / 64, MTP), 256, MMASM64>>>(
        pfh, pfl, hf + HF_WP, patch_proj_b, nullptr,
        tmp, nullptr, nullptr, MP, D, FD, 0);
    ln_kernel<<<(MP + 7) / 8, 256>>>(tmp, nullptr, patch_ln_g, patch_ln_b, patch_emb,
                                     nullptr, nullptr, MP);
    pe_kernel<<<(B * P * D + 255) / 256, 256>>>(patch_coords, row_embed, col_embed, peh, pel);
    mma_gemm_kernel<64><<<dim3(D / 64, MTP), 256, MMASM64>>>(
        peh, pel, hf + HF_WE, pe_proj_b, patch_emb,
        nullptr, pch, pcl, MP, D, D, 0);
    qinit_kernel<<<(MQ * D + 255) / 256, 256>>>(gene_queries, q, qh, ql);

    // ---- Stage B: decoder layers ----
    for (int l = 0; l < NL; l++) {
        const float* bq  = in_proj_b + (size_t)l * 3 * D;
        const float* bkv = bq + D;
        mma_gemm_kernel<64><<<dim3(D / 64, MT64), 256, MMASM64>>>(
            qh, ql, hf + HF_WQ + (size_t)l * D * D,
            bq, nullptr, Qb, nullptr, nullptr, MQ, D, D, 0);
        mma_gemm_kernel<64><<<dim3(2 * D / 64, MTP), 256, MMASM64>>>(
            pch, pcl, hf + HF_WK + (size_t)l * 2 * D * D,
            bkv, nullptr, kv, nullptr, nullptr, MP, 2 * D, D, 0);
        attn_kernel<<<dim3(B * H, (G + 31) / 32), 256>>>(Qb, kv, cxh, cxl);
        mma_gemm_kernel<64><<<dim3(D / 64, MT64), 256, MMASM64>>>(
            cxh, cxl, hf + HF_WO + (size_t)l * D * D,
            out_b + (size_t)l * D, nullptr, att, nullptr, nullptr, MQ, D, D, 0);
        ln_kernel<<<(MQ + 7) / 8, 256>>>(q, att, ln1_g + (size_t)l * D, ln1_b + (size_t)l * D,
                                         q, l1h, l1l, MQ);
        mma_gemm_kernel<128><<<dim3(4 * D / 64, MT128), 256, MMASM128>>>(
            l1h, l1l, hf + HF_F1 + (size_t)l * 4 * D * D,
            ff1_b + (size_t)l * 4 * D, nullptr, nullptr, fh, fl, MQ, 4 * D, D, 1);
        mma_gemm_kernel<64><<<dim3(D / 64, MT64), 256, MMASM64>>>(
            fh, fl, hf + HF_F2 + (size_t)l * 4 * D * D,
            ff2_b + (size_t)l * D, nullptr, att, nullptr, nullptr, MQ, D, 4 * D, 0);
        ln_kernel<<<(MQ + 7) / 8, 256>>>(q, att, ln2_g + (size_t)l * D, ln2_b + (size_t)l * D,
                                         q, qh, ql, MQ);
    }

    // ---- Stage C ----
    mma_gemm_kernel<64><<<dim3(HALF / 64, MT64), 256, MMASM64>>>(
        qh, ql, hf + HF_HD, head_b1, nullptr,
        qproj, nullptr, nullptr, MQ, HALF, D, 0);
    mma_gemm_kernel<64><<<dim3(HALF / 64, MTP), 256, MMASM64>>>(
        pch, pcl, hf + HF_HD, nullptr, nullptr,
        pproj, nullptr, nullptr, MP, HALF, D, 0);
    head_kernel<<<dim3(G / 8, B * P), 256>>>(qproj, pproj, out);
}